// round 2
// baseline (speedup 1.0000x reference)
#include <cuda_runtime.h>
#include <cstdint>

#define NTOK 6272
#define CDIM 1024
#define HEADS 16
#define HD 64
#define SFR 32
#define PTOK 196
#define MKV 1960
#define NSPLIT 2
#define KVHALF 980
#define CH 28
#define NCHUNK 35   // 980 / 28

// Scratch (no allocations allowed anywhere)
__device__ float g_qkv[3u * HEADS * NTOK * HD];               // [part][h][n][d]
__device__ float g_att[(size_t)NTOK * CDIM];                  // attention out, token-major
__device__ float g_pacc[(size_t)NSPLIT * SFR * HEADS * PTOK * HD];  // split partial numerators
__device__ float g_pl[NSPLIT * SFR * HEADS * PTOK];           // split partial denominators

// ---------------------------------------------------------------------------
// SGEMM: 128x128 tile, K-tile 8, 256 threads, 8x8 per thread.
// MODE 0: C = x @ W_qkv + b, scatter epilogue into g_qkv [part][h][n][d]
// MODE 1: C = g_att @ W_proj + b, plain row-major output
// ---------------------------------------------------------------------------
template <int MODE>
__global__ void __launch_bounds__(256, 2)
sgemm_kernel(const float* __restrict__ Aparam, const float* __restrict__ B,
             const float* __restrict__ bias, float* __restrict__ C, int Nc)
{
    const int K = 1024;
    const float* A = (MODE == 0) ? Aparam : (const float*)g_att;

    __shared__ float As[8][128];
    __shared__ float Bs[8][128];

    const int tid = threadIdx.x;
    const int bm = blockIdx.y * 128, bn = blockIdx.x * 128;
    const int arow = tid >> 1, acol = (tid & 1) << 2;
    const int brow = tid >> 5, bcol = (tid & 31) << 2;
    const int tx = tid & 15, ty = tid >> 4;

    const float* Aptr = A + (size_t)(bm + arow) * K + acol;
    const float* Bptr = B + (size_t)brow * Nc + bn + bcol;

    float acc[8][8];
#pragma unroll
    for (int i = 0; i < 8; i++)
#pragma unroll
        for (int j = 0; j < 8; j++) acc[i][j] = 0.f;

    float4 pa = *(const float4*)Aptr;
    float4 pb = *(const float4*)Bptr;

    for (int k0 = 0; k0 < K; k0 += 8) {
        As[acol + 0][arow] = pa.x;
        As[acol + 1][arow] = pa.y;
        As[acol + 2][arow] = pa.z;
        As[acol + 3][arow] = pa.w;
        *(float4*)&Bs[brow][bcol] = pb;
        __syncthreads();

        if (k0 + 8 < K) {
            pa = *(const float4*)(Aptr + k0 + 8);
            pb = *(const float4*)(Bptr + (size_t)(k0 + 8) * Nc);
        }

#pragma unroll
        for (int kk = 0; kk < 8; kk++) {
            float4 a0 = *(float4*)&As[kk][ty * 4];
            float4 a1 = *(float4*)&As[kk][64 + ty * 4];
            float4 b0 = *(float4*)&Bs[kk][tx * 4];
            float4 b1 = *(float4*)&Bs[kk][64 + tx * 4];
            float av[8] = {a0.x, a0.y, a0.z, a0.w, a1.x, a1.y, a1.z, a1.w};
            float bv[8] = {b0.x, b0.y, b0.z, b0.w, b1.x, b1.y, b1.z, b1.w};
#pragma unroll
            for (int i = 0; i < 8; i++)
#pragma unroll
                for (int j = 0; j < 8; j++) acc[i][j] += av[i] * bv[j];
        }
        __syncthreads();
    }

#pragma unroll
    for (int i = 0; i < 8; i++) {
        int m = bm + ((i < 4) ? (ty * 4 + i) : (64 + ty * 4 + (i - 4)));
#pragma unroll
        for (int j = 0; j < 8; j++) {
            int col = bn + ((j < 4) ? (tx * 4 + j) : (64 + tx * 4 + (j - 4)));
            float val = acc[i][j] + bias[col];
            if (MODE == 0) {
                int part = col >> 10;
                int hd = col & 1023;
                int h = hd >> 6;
                int d = hd & 63;
                g_qkv[(((size_t)part * HEADS + h) * NTOK + m) * HD + d] = val;
            } else {
                C[(size_t)m * Nc + col] = val;
            }
        }
    }
}

// ---------------------------------------------------------------------------
// LayerNorm over D=64 on q (part 0) and k (part 1). One warp per vector.
// ---------------------------------------------------------------------------
__global__ void __launch_bounds__(256)
ln_kernel(const float* __restrict__ qg, const float* __restrict__ qb,
          const float* __restrict__ kg, const float* __restrict__ kb)
{
    const int NV = 2 * HEADS * NTOK;
    int warp = (blockIdx.x * blockDim.x + threadIdx.x) >> 5;
    int lane = threadIdx.x & 31;
    if (warp >= NV) return;

    float* v = g_qkv + (size_t)warp * HD;
    float2 x = *(float2*)&v[lane * 2];

    float s = x.x + x.y;
#pragma unroll
    for (int o = 16; o; o >>= 1) s += __shfl_xor_sync(0xffffffffu, s, o);
    float mu = s * (1.f / 64.f);

    float dx = x.x - mu, dy = x.y - mu;
    float ss = dx * dx + dy * dy;
#pragma unroll
    for (int o = 16; o; o >>= 1) ss += __shfl_xor_sync(0xffffffffu, ss, o);
    float rstd = rsqrtf(ss * (1.f / 64.f) + 1e-6f);

    bool isq = warp < HEADS * NTOK;
    const float* g = isq ? qg : kg;
    const float* b = isq ? qb : kb;
    x.x = dx * rstd * g[lane * 2] + b[lane * 2];
    x.y = dy * rstd * g[lane * 2 + 1] + b[lane * 2 + 1];
    *(float2*)&v[lane * 2] = x;
}

// ---------------------------------------------------------------------------
// Sparse attention v2.
// Block = (frame s, head h, kv-split). 448 threads = 14 warps.
// Lane pair (2p, 2p+1) handles query p: each thread holds HALF of q (32 dims)
// and HALF of the output accumulator; half-dots combined via shfl.xor(1).
// Softmax uses a STATIC max of 10 (valid since ||q||=||k||=8 after LN with
// gamma=1,beta=0 => |score| <= 8), so split partials are purely additive.
// K/V chunk for the next iteration is prefetched into registers.
// ---------------------------------------------------------------------------
__global__ void __launch_bounds__(448)
attn2_kernel(const int* __restrict__ gidx, const float* __restrict__ abias)
{
    const int s = blockIdx.x;
    const int h = blockIdx.y;
    const int split = blockIdx.z;

    const float* qbuf = g_qkv + (size_t)h * NTOK * HD;
    const float* kbuf = g_qkv + (size_t)(HEADS + h) * NTOK * HD;
    const float* vbuf = g_qkv + (size_t)(2 * HEADS + h) * NTOK * HD;

    __shared__ float Ks[CH][HD];
    __shared__ float Vs[CH][HD];
    __shared__ float bias_s[CH];

    const int tid = threadIdx.x;
    const int p = tid >> 1;
    const int half = tid & 1;
    const int prow = (p < PTOK) ? p : 0;   // clamp so all warps stay converged

    // this thread's half of q
    float4 qv[8];
    {
        const float4* qp =
            (const float4*)(qbuf + (size_t)(s * PTOK + prow) * HD + half * 32);
#pragma unroll
        for (int i = 0; i < 8; i++) qv[i] = qp[i];
    }

    // prefetch mapping: chunk has CH*32 = 896 float4s; this thread owns
    // elements tid and tid+448.
    const int j0 = tid >> 5;         // key 0..13
    const int j1 = j0 + 14;          // key 14..27
    const int inner = tid & 31;      // 0..15 -> K float4s, 16..31 -> V float4s
    const bool isK = inner < 16;
    const int c4 = isK ? inner : inner - 16;
    float* dst0 = (isK ? &Ks[j0][0] : &Vs[j0][0]) + c4 * 4;
    float* dst1 = (isK ? &Ks[j1][0] : &Vs[j1][0]) + c4 * 4;
    const float* src = (isK ? kbuf : vbuf) + c4 * 4;

    const int gbase = s * MKV + split * KVHALF;

    // prefetch chunk 0
    float4 pk0, pk1;
    float pbias = 0.f;
    {
        int tok0 = gidx[gbase + j0];
        int tok1 = gidx[gbase + j1];
        pk0 = *(const float4*)(src + (size_t)tok0 * HD);
        pk1 = *(const float4*)(src + (size_t)tok1 * HD);
        if (tid < CH) pbias = abias[gbase + tid] - 10.f;  // fold static max
    }

    float l = 0.f;
    float4 acc[8];
#pragma unroll
    for (int i = 0; i < 8; i++) acc[i] = make_float4(0.f, 0.f, 0.f, 0.f);

    for (int c = 0; c < NCHUNK; c++) {
        __syncthreads();                    // previous chunk's compute done
        *(float4*)dst0 = pk0;
        *(float4*)dst1 = pk1;
        if (tid < CH) bias_s[tid] = pbias;
        __syncthreads();

        if (c + 1 < NCHUNK) {               // prefetch next chunk -> registers
            int cb = gbase + (c + 1) * CH;
            int tok0 = gidx[cb + j0];
            int tok1 = gidx[cb + j1];
            pk0 = *(const float4*)(src + (size_t)tok0 * HD);
            pk1 = *(const float4*)(src + (size_t)tok1 * HD);
            if (tid < CH) pbias = abias[cb + tid] - 10.f;
        }

#pragma unroll
        for (int j = 0; j < CH; j++) {
            const float4* kr = (const float4*)&Ks[j][half * 32];
            float d0 = 0.f, d1 = 0.f, d2 = 0.f, d3 = 0.f;
#pragma unroll
            for (int t = 0; t < 8; t++) {
                float4 kk = kr[t];
                d0 += qv[t].x * kk.x;
                d1 += qv[t].y * kk.y;
                d2 += qv[t].z * kk.z;
                d3 += qv[t].w * kk.w;
            }
            float sh = (d0 + d1) + (d2 + d3);
            float sfull = sh + __shfl_xor_sync(0xffffffffu, sh, 1);
            float pj = __expf(fmaf(sfull, 0.125f, bias_s[j]));
            l += pj;
            const float4* vr = (const float4*)&Vs[j][half * 32];
#pragma unroll
            for (int t = 0; t < 8; t++) {
                float4 vv = vr[t];
                acc[t].x += pj * vv.x;
                acc[t].y += pj * vv.y;
                acc[t].z += pj * vv.z;
                acc[t].w += pj * vv.w;
            }
        }
    }

    if (p < PTOK) {
        size_t row = ((size_t)(split * SFR + s) * HEADS + h) * PTOK + p;
        float4* op = (float4*)(g_pacc + row * HD + half * 32);
#pragma unroll
        for (int i = 0; i < 8; i++) op[i] = acc[i];
        if (half == 0) g_pl[row] = l;
    }
}

// ---------------------------------------------------------------------------
// Combine the two KV-split partials: out = (acc0+acc1)/(l0+l1), scatter into
// token-major g_att for the projection GEMM.
// ---------------------------------------------------------------------------
__global__ void __launch_bounds__(256)
combine_kernel()
{
    int idx = blockIdx.x * blockDim.x + threadIdx.x;
    const int total = SFR * HEADS * PTOK * (HD / 4);
    if (idx >= total) return;
    int c4 = idx & 15;
    int shp = idx >> 4;                       // (s*HEADS+h)*PTOK + p
    size_t row0 = shp;
    size_t row1 = (size_t)SFR * HEADS * PTOK + shp;
    float4 a = ((const float4*)(g_pacc + row0 * HD))[c4];
    float4 b = ((const float4*)(g_pacc + row1 * HD))[c4];
    float inv = 1.f / (g_pl[row0] + g_pl[row1]);
    float4 o;
    o.x = (a.x + b.x) * inv;
    o.y = (a.y + b.y) * inv;
    o.z = (a.z + b.z) * inv;
    o.w = (a.w + b.w) * inv;
    int pp = shp % PTOK;
    int sh = shp / PTOK;
    int hh = sh % HEADS;
    int ss = sh / HEADS;
    ((float4*)(g_att + (size_t)(ss * PTOK + pp) * CDIM + hh * HD))[c4] = o;
}

// ---------------------------------------------------------------------------
extern "C" void kernel_launch(void* const* d_in, const int* in_sizes, int n_in,
                              void* d_out, int out_size)
{
    const float* x     = (const float*)d_in[0];
    const float* Wqkv  = (const float*)d_in[1];
    const float* bqkv  = (const float*)d_in[2];
    const float* qg    = (const float*)d_in[3];
    const float* qb    = (const float*)d_in[4];
    const float* kg    = (const float*)d_in[5];
    const float* kb    = (const float*)d_in[6];
    const float* Wproj = (const float*)d_in[7];
    const float* bproj = (const float*)d_in[8];
    const int*   gidx  = (const int*)d_in[9];
    const float* abias = (const float*)d_in[10];
    float* out = (float*)d_out;

    // 1) QKV GEMM with scatter epilogue: 6272 x 3072 x 1024
    {
        dim3 grid(3072 / 128, NTOK / 128);
        sgemm_kernel<0><<<grid, 256>>>(x, Wqkv, bqkv, nullptr, 3072);
    }
    // 2) LayerNorm q/k per (head, token) over D=64
    {
        int nvec = 2 * HEADS * NTOK;
        int blocks = (nvec * 32 + 255) / 256;
        ln_kernel<<<blocks, 256>>>(qg, qb, kg, kb);
    }
    // 3) Sparse attention: (frame, head, kv-split)
    {
        dim3 grid(SFR, HEADS, NSPLIT);
        attn2_kernel<<<grid, 448>>>(gidx, abias);
    }
    // 3b) Combine split partials into g_att
    {
        const int total = SFR * HEADS * PTOK * (HD / 4);
        combine_kernel<<<(total + 255) / 256, 256>>>();
    }
    // 4) Output projection: 6272 x 1024 x 1024 -> d_out
    {
        dim3 grid(1024 / 128, NTOK / 128);
        sgemm_kernel<1><<<grid, 256>>>(nullptr, Wproj, bproj, out, 1024);
    }
}

// round 3
// speedup vs baseline: 1.5947x; 1.5947x over previous
#include <cuda_runtime.h>
#include <cstdint>

#define NTOK 6272
#define CDIM 1024
#define HEADS 16
#define HD 64
#define SFR 32
#define PTOK 196
#define MKV 1960
#define KT 32          // keys per tile
#define NT 62          // ceil(1960/32)
#define RPAD 68        // padded row stride (floats) for Q/K/V smem
#define PPAD 36        // padded row stride for P smem

// Scratch (no allocations allowed anywhere)
__device__ float g_qkv[3u * HEADS * NTOK * HD];   // [part][h][n][d]
__device__ float g_att[(size_t)NTOK * CDIM];      // attention out, token-major

// ---------------------------------------------------------------------------
// SGEMM: 128x128 tile, K-tile 8, 256 threads, 8x8 per thread.
// MODE 0: C = x @ W_qkv + b, scatter epilogue into g_qkv [part][h][n][d]
// MODE 1: C = g_att @ W_proj + b, plain row-major output
// ---------------------------------------------------------------------------
template <int MODE>
__global__ void __launch_bounds__(256, 2)
sgemm_kernel(const float* __restrict__ Aparam, const float* __restrict__ B,
             const float* __restrict__ bias, float* __restrict__ C, int Nc)
{
    const int K = 1024;
    const float* A = (MODE == 0) ? Aparam : (const float*)g_att;

    __shared__ float As[8][128];
    __shared__ float Bs[8][128];

    const int tid = threadIdx.x;
    const int bm = blockIdx.y * 128, bn = blockIdx.x * 128;
    const int arow = tid >> 1, acol = (tid & 1) << 2;
    const int brow = tid >> 5, bcol = (tid & 31) << 2;
    const int tx = tid & 15, ty = tid >> 4;

    const float* Aptr = A + (size_t)(bm + arow) * K + acol;
    const float* Bptr = B + (size_t)brow * Nc + bn + bcol;

    float acc[8][8];
#pragma unroll
    for (int i = 0; i < 8; i++)
#pragma unroll
        for (int j = 0; j < 8; j++) acc[i][j] = 0.f;

    float4 pa = *(const float4*)Aptr;
    float4 pb = *(const float4*)Bptr;

    for (int k0 = 0; k0 < K; k0 += 8) {
        As[acol + 0][arow] = pa.x;
        As[acol + 1][arow] = pa.y;
        As[acol + 2][arow] = pa.z;
        As[acol + 3][arow] = pa.w;
        *(float4*)&Bs[brow][bcol] = pb;
        __syncthreads();

        if (k0 + 8 < K) {
            pa = *(const float4*)(Aptr + k0 + 8);
            pb = *(const float4*)(Bptr + (size_t)(k0 + 8) * Nc);
        }

#pragma unroll
        for (int kk = 0; kk < 8; kk++) {
            float4 a0 = *(float4*)&As[kk][ty * 4];
            float4 a1 = *(float4*)&As[kk][64 + ty * 4];
            float4 b0 = *(float4*)&Bs[kk][tx * 4];
            float4 b1 = *(float4*)&Bs[kk][64 + tx * 4];
            float av[8] = {a0.x, a0.y, a0.z, a0.w, a1.x, a1.y, a1.z, a1.w};
            float bv[8] = {b0.x, b0.y, b0.z, b0.w, b1.x, b1.y, b1.z, b1.w};
#pragma unroll
            for (int i = 0; i < 8; i++)
#pragma unroll
                for (int j = 0; j < 8; j++) acc[i][j] += av[i] * bv[j];
        }
        __syncthreads();
    }

#pragma unroll
    for (int i = 0; i < 8; i++) {
        int m = bm + ((i < 4) ? (ty * 4 + i) : (64 + ty * 4 + (i - 4)));
#pragma unroll
        for (int j = 0; j < 8; j++) {
            int col = bn + ((j < 4) ? (tx * 4 + j) : (64 + tx * 4 + (j - 4)));
            float val = acc[i][j] + bias[col];
            if (MODE == 0) {
                int part = col >> 10;
                int hd = col & 1023;
                int h = hd >> 6;
                int d = hd & 63;
                g_qkv[(((size_t)part * HEADS + h) * NTOK + m) * HD + d] = val;
            } else {
                C[(size_t)m * Nc + col] = val;
            }
        }
    }
}

// ---------------------------------------------------------------------------
// LayerNorm over D=64 on q (part 0) and k (part 1). One warp per vector.
// ---------------------------------------------------------------------------
__global__ void __launch_bounds__(256)
ln_kernel(const float* __restrict__ qg, const float* __restrict__ qb,
          const float* __restrict__ kg, const float* __restrict__ kb)
{
    const int NV = 2 * HEADS * NTOK;
    int warp = (blockIdx.x * blockDim.x + threadIdx.x) >> 5;
    int lane = threadIdx.x & 31;
    if (warp >= NV) return;

    float* v = g_qkv + (size_t)warp * HD;
    float2 x = *(float2*)&v[lane * 2];

    float s = x.x + x.y;
#pragma unroll
    for (int o = 16; o; o >>= 1) s += __shfl_xor_sync(0xffffffffu, s, o);
    float mu = s * (1.f / 64.f);

    float dx = x.x - mu, dy = x.y - mu;
    float ss = dx * dx + dy * dy;
#pragma unroll
    for (int o = 16; o; o >>= 1) ss += __shfl_xor_sync(0xffffffffu, ss, o);
    float rstd = rsqrtf(ss * (1.f / 64.f) + 1e-6f);

    bool isq = warp < HEADS * NTOK;
    const float* g = isq ? qg : kg;
    const float* b = isq ? qb : kb;
    x.x = dx * rstd * g[lane * 2] + b[lane * 2];
    x.y = dy * rstd * g[lane * 2 + 1] + b[lane * 2 + 1];
    *(float2*)&v[lane * 2] = x;
}

// ---------------------------------------------------------------------------
// Sparse attention v3: GEMM-shaped flash. One block per (s,h).
// 224 threads = 28(ty) x 8(tx). Per 32-key tile:
//   QK: thread tile 7 queries x 4 keys (keys tx+8j), Q persistent in smem.
//   exp with STATIC max 10 (||q||=||k||=8 after LN => |score|<=8) -> additive.
//   P staged through smem, PV: thread tile 7 queries x 8 dims (dims tx*8..).
// l reduced over tx lanes once at the end; writes g_att directly.
// ---------------------------------------------------------------------------
__global__ void __launch_bounds__(224, 2)
attn3_kernel(const int* __restrict__ gidx, const float* __restrict__ abias)
{
    extern __shared__ float sm[];
    float* Qs = sm;                          // 196 * RPAD
    float* Ks = Qs + PTOK * RPAD;            // KT * RPAD
    float* Vs = Ks + KT * RPAD;              // KT * RPAD
    float* Ps = Vs + KT * RPAD;              // 196 * PPAD
    float* Bs = Ps + PTOK * PPAD;            // KT

    const int s = blockIdx.x;
    const int h = blockIdx.y;
    const int tid = threadIdx.x;
    const int tx = tid & 7;
    const int ty = tid >> 3;

    const float* qbuf = g_qkv + ((size_t)h * NTOK + (size_t)s * PTOK) * HD;
    const float* kbuf = g_qkv + (size_t)(HEADS + h) * NTOK * HD;
    const float* vbuf = g_qkv + (size_t)(2 * HEADS + h) * NTOK * HD;

    // Load Q tile (196 x 64) into padded smem
    for (int i = tid; i < PTOK * 16; i += 224) {
        int q = i >> 4, c4 = i & 15;
        float4 v = ((const float4*)qbuf)[i];
        *(float4*)&Qs[q * RPAD + c4 * 4] = v;
    }

    float accO[7][8];
    float l[7];
#pragma unroll
    for (int i = 0; i < 7; i++) {
        l[i] = 0.f;
#pragma unroll
        for (int d = 0; d < 8; d++) accO[i][d] = 0.f;
    }

    const int gbase = s * MKV;

    for (int t = 0; t < NT; t++) {
        __syncthreads();   // prev tile's PV done reading Vs/Ps; QK done with Ks
        const int t0 = t * KT;
        // gathered K/V tile load: 64 rows x 16 float4
        for (int i = tid; i < KT * 2 * 16; i += 224) {
            int row = i >> 4, c4 = i & 15;
            int key = row & (KT - 1);
            int gpos = t0 + key;
            int tok = gidx[gbase + (gpos < MKV ? gpos : 0)];
            const float* src = (row < KT ? kbuf : vbuf) + (size_t)tok * HD + c4 * 4;
            float* dst = (row < KT ? Ks : Vs) + key * RPAD + c4 * 4;
            *(float4*)dst = *(const float4*)src;
        }
        if (tid < KT) {
            int gpos = t0 + tid;
            Bs[tid] = (gpos < MKV) ? abias[gbase + gpos] - 10.f : -1e9f;
        }
        __syncthreads();

        // ---- QK: 7x4 register tile ----
        float acc[7][4];
#pragma unroll
        for (int i = 0; i < 7; i++)
#pragma unroll
            for (int j = 0; j < 4; j++) acc[i][j] = 0.f;

#pragma unroll
        for (int kk = 0; kk < 16; kk++) {
            float4 kv[4];
#pragma unroll
            for (int j = 0; j < 4; j++)
                kv[j] = *(float4*)&Ks[(tx + 8 * j) * RPAD + kk * 4];
#pragma unroll
            for (int i = 0; i < 7; i++) {
                float4 qv = *(float4*)&Qs[(ty * 7 + i) * RPAD + kk * 4];
#pragma unroll
                for (int j = 0; j < 4; j++) {
                    acc[i][j] += qv.x * kv[j].x;
                    acc[i][j] += qv.y * kv[j].y;
                    acc[i][j] += qv.z * kv[j].z;
                    acc[i][j] += qv.w * kv[j].w;
                }
            }
        }

        // ---- softmax weights (static max), stage P ----
        float bj[4];
#pragma unroll
        for (int j = 0; j < 4; j++) bj[j] = Bs[tx + 8 * j];
#pragma unroll
        for (int i = 0; i < 7; i++) {
#pragma unroll
            for (int j = 0; j < 4; j++) {
                float p = __expf(fmaf(acc[i][j], 0.125f, bj[j]));
                l[i] += p;
                Ps[(ty * 7 + i) * PPAD + tx + 8 * j] = p;
            }
        }
        __syncthreads();

        // ---- PV: 7x8 register tile over 32 keys ----
#pragma unroll 4
        for (int kk = 0; kk < KT; kk++) {
            float4 v0 = *(float4*)&Vs[kk * RPAD + tx * 8];
            float4 v1 = *(float4*)&Vs[kk * RPAD + tx * 8 + 4];
#pragma unroll
            for (int i = 0; i < 7; i++) {
                float p = Ps[(ty * 7 + i) * PPAD + kk];
                accO[i][0] += p * v0.x;
                accO[i][1] += p * v0.y;
                accO[i][2] += p * v0.z;
                accO[i][3] += p * v0.w;
                accO[i][4] += p * v1.x;
                accO[i][5] += p * v1.y;
                accO[i][6] += p * v1.z;
                accO[i][7] += p * v1.w;
            }
        }
    }

    // reduce l over the 8 tx lanes (lanes with same ty are consecutive)
#pragma unroll
    for (int i = 0; i < 7; i++) {
        float v = l[i];
        v += __shfl_xor_sync(0xffffffffu, v, 1);
        v += __shfl_xor_sync(0xffffffffu, v, 2);
        v += __shfl_xor_sync(0xffffffffu, v, 4);
        l[i] = v;
    }

    // write output
#pragma unroll
    for (int i = 0; i < 7; i++) {
        int q = ty * 7 + i;
        float inv = 1.f / l[i];
        float* op = g_att + (size_t)(s * PTOK + q) * CDIM + h * HD + tx * 8;
        float4 o0, o1;
        o0.x = accO[i][0] * inv; o0.y = accO[i][1] * inv;
        o0.z = accO[i][2] * inv; o0.w = accO[i][3] * inv;
        o1.x = accO[i][4] * inv; o1.y = accO[i][5] * inv;
        o1.z = accO[i][6] * inv; o1.w = accO[i][7] * inv;
        *(float4*)op = o0;
        *(float4*)(op + 4) = o1;
    }
}

// ---------------------------------------------------------------------------
extern "C" void kernel_launch(void* const* d_in, const int* in_sizes, int n_in,
                              void* d_out, int out_size)
{
    const float* x     = (const float*)d_in[0];
    const float* Wqkv  = (const float*)d_in[1];
    const float* bqkv  = (const float*)d_in[2];
    const float* qg    = (const float*)d_in[3];
    const float* qb    = (const float*)d_in[4];
    const float* kg    = (const float*)d_in[5];
    const float* kb    = (const float*)d_in[6];
    const float* Wproj = (const float*)d_in[7];
    const float* bproj = (const float*)d_in[8];
    const int*   gidx  = (const int*)d_in[9];
    const float* abias = (const float*)d_in[10];
    float* out = (float*)d_out;

    // 1) QKV GEMM with scatter epilogue: 6272 x 3072 x 1024
    {
        dim3 grid(3072 / 128, NTOK / 128);
        sgemm_kernel<0><<<grid, 256>>>(x, Wqkv, bqkv, nullptr, 3072);
    }
    // 2) LayerNorm q/k per (head, token) over D=64
    {
        int nvec = 2 * HEADS * NTOK;
        int blocks = (nvec * 32 + 255) / 256;
        ln_kernel<<<blocks, 256>>>(qg, qb, kg, kb);
    }
    // 3) Sparse attention per (frame, head)
    {
        const int smem_bytes =
            (PTOK * RPAD + 2 * KT * RPAD + PTOK * PPAD + KT) * (int)sizeof(float);
        static int attr_set = 0;
        if (!attr_set) {
            cudaFuncSetAttribute(attn3_kernel,
                                 cudaFuncAttributeMaxDynamicSharedMemorySize,
                                 smem_bytes);
            attr_set = 1;
        }
        dim3 grid(SFR, HEADS);
        attn3_kernel<<<grid, 224, smem_bytes>>>(gidx, abias);
    }
    // 4) Output projection: 6272 x 1024 x 1024 -> d_out
    {
        dim3 grid(1024 / 128, NTOK / 128);
        sgemm_kernel<1><<<grid, 256>>>(nullptr, Wproj, bproj, out, 1024);
    }
}

// round 5
// speedup vs baseline: 1.8850x; 1.1820x over previous
#include <cuda_runtime.h>
#include <cuda_bf16.h>
#include <cstdint>

#define NTOK 6272
#define CDIM 1024
#define HEADS 16
#define HD 64
#define SFR 32
#define PTOK 196
#define MKV 1960
#define KT 32
#define NT 62
#define RPAD 68
#define PPAD 36

#define KDIM 1024
#define NQKV 3072

// Scratch (no allocations anywhere)
__device__ float g_qkv[3u * HEADS * NTOK * HD];
__device__ float g_att[(size_t)NTOK * CDIM];
__device__ __nv_bfloat16 g_ahi[(size_t)NTOK * KDIM];
__device__ __nv_bfloat16 g_alo[(size_t)NTOK * KDIM];
__device__ __nv_bfloat16 g_wqhi[(size_t)NQKV * KDIM];
__device__ __nv_bfloat16 g_wqlo[(size_t)NQKV * KDIM];
__device__ __nv_bfloat16 g_wphi[(size_t)1024 * KDIM];
__device__ __nv_bfloat16 g_wplo[(size_t)1024 * KDIM];

// ---------------------------------------------------------------------------
// helpers
// ---------------------------------------------------------------------------
__device__ __forceinline__ uint32_t smem_u32(const void* p) {
    uint32_t a;
    asm("{ .reg .u64 t; cvta.to.shared.u64 t, %1; cvt.u32.u64 %0, t; }"
        : "=r"(a) : "l"(p));
    return a;
}
__device__ __forceinline__ void ldsm4(uint32_t addr, uint32_t& r0, uint32_t& r1,
                                      uint32_t& r2, uint32_t& r3) {
    asm volatile("ldmatrix.sync.aligned.m8n8.x4.shared.b16 {%0,%1,%2,%3}, [%4];"
                 : "=r"(r0), "=r"(r1), "=r"(r2), "=r"(r3) : "r"(addr));
}
__device__ __forceinline__ void mma_bf16(float& d0, float& d1, float& d2, float& d3,
                                         uint32_t a0, uint32_t a1, uint32_t a2, uint32_t a3,
                                         uint32_t b0, uint32_t b1) {
    asm volatile(
        "mma.sync.aligned.m16n8k16.row.col.f32.bf16.bf16.f32 "
        "{%0,%1,%2,%3}, {%4,%5,%6,%7}, {%8,%9}, {%0,%1,%2,%3};"
        : "+f"(d0), "+f"(d1), "+f"(d2), "+f"(d3)
        : "r"(a0), "r"(a1), "r"(a2), "r"(a3), "r"(b0), "r"(b1));
}

// ---------------------------------------------------------------------------
// Split fp32 -> bf16 hi/lo planes into g_ahi/g_alo (same layout)
// ---------------------------------------------------------------------------
__global__ void __launch_bounds__(256)
split_kernel(const float* __restrict__ src, int n4)
{
    int i = blockIdx.x * blockDim.x + threadIdx.x;
    if (i >= n4) return;
    float4 a = ((const float4*)src)[i];
    __nv_bfloat16 h0 = __float2bfloat16_rn(a.x);
    __nv_bfloat16 h1 = __float2bfloat16_rn(a.y);
    __nv_bfloat16 h2 = __float2bfloat16_rn(a.z);
    __nv_bfloat16 h3 = __float2bfloat16_rn(a.w);
    __nv_bfloat16 l0 = __float2bfloat16_rn(a.x - __bfloat162float(h0));
    __nv_bfloat16 l1 = __float2bfloat16_rn(a.y - __bfloat162float(h1));
    __nv_bfloat16 l2 = __float2bfloat16_rn(a.z - __bfloat162float(h2));
    __nv_bfloat16 l3 = __float2bfloat16_rn(a.w - __bfloat162float(h3));
    __nv_bfloat162 hh0; hh0.x = h0; hh0.y = h1;
    __nv_bfloat162 hh1; hh1.x = h2; hh1.y = h3;
    __nv_bfloat162 ll0; ll0.x = l0; ll0.y = l1;
    __nv_bfloat162 ll1; ll1.x = l2; ll1.y = l3;
    ((__nv_bfloat162*)g_ahi)[i * 2]     = hh0;
    ((__nv_bfloat162*)g_ahi)[i * 2 + 1] = hh1;
    ((__nv_bfloat162*)g_alo)[i * 2]     = ll0;
    ((__nv_bfloat162*)g_alo)[i * 2 + 1] = ll1;
}

// ---------------------------------------------------------------------------
// Transpose + split: W [1024][N] fp32 -> hi/lo [N][1024] bf16
// WHICH 0: -> g_wqhi/g_wqlo (N=3072); WHICH 1: -> g_wphi/g_wplo (N=1024)
// ---------------------------------------------------------------------------
template <int WHICH>
__global__ void __launch_bounds__(256)
wsplit_kernel(const float* __restrict__ W, int N)
{
    __nv_bfloat16* hi = (WHICH == 0) ? g_wqhi : g_wphi;
    __nv_bfloat16* lo = (WHICH == 0) ? g_wqlo : g_wplo;
    __shared__ float t[32][33];
    int n0 = blockIdx.x * 32, k0 = blockIdx.y * 32;
    int tx = threadIdx.x & 31, ty = threadIdx.x >> 5;
#pragma unroll
    for (int r = 0; r < 4; r++)
        t[ty + r * 8][tx] = W[(size_t)(k0 + ty + r * 8) * N + n0 + tx];
    __syncthreads();
#pragma unroll
    for (int r = 0; r < 4; r++) {
        int n = ty + r * 8;
        float a = t[tx][n];
        __nv_bfloat16 h = __float2bfloat16_rn(a);
        __nv_bfloat16 l = __float2bfloat16_rn(a - __bfloat162float(h));
        size_t o = (size_t)(n0 + n) * KDIM + k0 + tx;
        hi[o] = h;
        lo[o] = l;
    }
}

// ---------------------------------------------------------------------------
// HMMA (mma.sync bf16 hi/lo-split) GEMM. CTA 128x128, 8 warps (64x32 each),
// k-chunk 16, double-buffered smem, 48B row stride for conflict-free ldmatrix.
// D = Ahi*Bhi + Ahi*Blo + Alo*Bhi, fp32 accum.
// MODE 0: A=g_ahi/lo, B=g_wq*, scatter C(+bias) into g_qkv [part][h][n][d]
// MODE 1: A=g_ahi/lo, B=g_wp*, row-major C(+bias) -> Cout
// ---------------------------------------------------------------------------
#define RSTR 24                       // smem row stride in bf16 elems (48B)
#define TILE_E (128 * RSTR)           // 3072 elems per tile
#define STAGE_E (4 * TILE_E)          // Ahi,Alo,Bhi,Blo
#define STAGE_B (STAGE_E * 2)         // 24576 bytes
#define OFF_AH 0
#define OFF_AL TILE_E
#define OFF_BH (2 * TILE_E)
#define OFF_BL (3 * TILE_E)

template <int MODE>
__global__ void __launch_bounds__(256)
hmma_gemm_kernel(const float* __restrict__ bias, float* __restrict__ Cout, int Nc)
{
    extern __shared__ __nv_bfloat16 smb[];
    const uint32_t su = smem_u32(smb);

    const __nv_bfloat16* Bhi = (MODE == 0) ? g_wqhi : g_wphi;
    const __nv_bfloat16* Blo = (MODE == 0) ? g_wqlo : g_wplo;

    const int tid = threadIdx.x;
    const int wid = tid >> 5;
    const int lane = tid & 31;
    const int wm = wid & 1;            // 2 warps along M
    const int wn = wid >> 1;           // 4 warps along N
    const int bm = blockIdx.y * 128;
    const int bn = blockIdx.x * 128;

    // global load mapping: row = tid/2 (0..127), half = tid&1 (16B each)
    const int grow = tid >> 1;
    const int ghalf = tid & 1;
    const __nv_bfloat16* pAhi = g_ahi + (size_t)(bm + grow) * KDIM + ghalf * 8;
    const __nv_bfloat16* pAlo = g_alo + (size_t)(bm + grow) * KDIM + ghalf * 8;
    const __nv_bfloat16* pBhi = Bhi + (size_t)(bn + grow) * KDIM + ghalf * 8;
    const __nv_bfloat16* pBlo = Blo + (size_t)(bn + grow) * KDIM + ghalf * 8;
    const uint32_t sstore = (uint32_t)(grow * RSTR + ghalf * 8) * 2;  // bytes

    // ldmatrix source addressing (element units within a tile)
    const uint32_t aAddr = (uint32_t)((wm * 64 + (lane & 15)) * RSTR + (lane >> 4) * 8);
    const uint32_t bAddr = (uint32_t)((wn * 32 + (lane & 7) + ((lane >> 4) & 1) * 8) * RSTR
                                      + ((lane >> 3) & 1) * 8);

    float acc[4][4][4];
#pragma unroll
    for (int mf = 0; mf < 4; mf++)
#pragma unroll
        for (int nf = 0; nf < 4; nf++)
#pragma unroll
            for (int e = 0; e < 4; e++) acc[mf][nf][e] = 0.f;

    // prefetch chunk 0
    uint4 rah = *(const uint4*)pAhi;
    uint4 ral = *(const uint4*)pAlo;
    uint4 rbh = *(const uint4*)pBhi;
    uint4 rbl = *(const uint4*)pBlo;
    {
        char* s0 = (char*)smb;
        *(uint4*)(s0 + OFF_AH * 2 + sstore) = rah;
        *(uint4*)(s0 + OFF_AL * 2 + sstore) = ral;
        *(uint4*)(s0 + OFF_BH * 2 + sstore) = rbh;
        *(uint4*)(s0 + OFF_BL * 2 + sstore) = rbl;
    }
    __syncthreads();

    const int NCHUNK = KDIM / 16;      // 64
    for (int c = 0; c < NCHUNK; c++) {
        if (c + 1 < NCHUNK) {          // prefetch next chunk into regs
            int ko = (c + 1) * 16;
            rah = *(const uint4*)(pAhi + ko);
            ral = *(const uint4*)(pAlo + ko);
            rbh = *(const uint4*)(pBhi + ko);
            rbl = *(const uint4*)(pBlo + ko);
        }

        const uint32_t sb = su + (uint32_t)(c & 1) * STAGE_B;
        // B fragments: 4 n8 frags hi + lo
        uint32_t bh[8], bl[8];
        ldsm4(sb + (OFF_BH + bAddr) * 2, bh[0], bh[1], bh[2], bh[3]);
        ldsm4(sb + (OFF_BH + bAddr + 16 * RSTR) * 2, bh[4], bh[5], bh[6], bh[7]);
        ldsm4(sb + (OFF_BL + bAddr) * 2, bl[0], bl[1], bl[2], bl[3]);
        ldsm4(sb + (OFF_BL + bAddr + 16 * RSTR) * 2, bl[4], bl[5], bl[6], bl[7]);

#pragma unroll
        for (int mf = 0; mf < 4; mf++) {
            uint32_t a0, a1, a2, a3;
            ldsm4(sb + (OFF_AH + aAddr + mf * 16 * RSTR) * 2, a0, a1, a2, a3);
#pragma unroll
            for (int nf = 0; nf < 4; nf++)
                mma_bf16(acc[mf][nf][0], acc[mf][nf][1], acc[mf][nf][2], acc[mf][nf][3],
                         a0, a1, a2, a3, bh[nf * 2], bh[nf * 2 + 1]);
#pragma unroll
            for (int nf = 0; nf < 4; nf++)
                mma_bf16(acc[mf][nf][0], acc[mf][nf][1], acc[mf][nf][2], acc[mf][nf][3],
                         a0, a1, a2, a3, bl[nf * 2], bl[nf * 2 + 1]);
            ldsm4(sb + (OFF_AL + aAddr + mf * 16 * RSTR) * 2, a0, a1, a2, a3);
#pragma unroll
            for (int nf = 0; nf < 4; nf++)
                mma_bf16(acc[mf][nf][0], acc[mf][nf][1], acc[mf][nf][2], acc[mf][nf][3],
                         a0, a1, a2, a3, bh[nf * 2], bh[nf * 2 + 1]);
        }

        if (c + 1 < NCHUNK) {          // store prefetched regs into other stage
            char* sd = (char*)smb + ((c + 1) & 1) * STAGE_B;
            *(uint4*)(sd + OFF_AH * 2 + sstore) = rah;
            *(uint4*)(sd + OFF_AL * 2 + sstore) = ral;
            *(uint4*)(sd + OFF_BH * 2 + sstore) = rbh;
            *(uint4*)(sd + OFF_BL * 2 + sstore) = rbl;
        }
        __syncthreads();
    }

    // epilogue: acc frag (mf,nf): d0,d1 -> (row lane/4, col 2*(lane&3)), d2,d3 -> row+8
#pragma unroll
    for (int mf = 0; mf < 4; mf++) {
#pragma unroll
        for (int nf = 0; nf < 4; nf++) {
            int m0 = bm + wm * 64 + mf * 16 + (lane >> 2);
            int col = bn + wn * 32 + nf * 8 + (lane & 3) * 2;
            float2 bb = *(const float2*)&bias[col];
            float2 v0, v1;
            v0.x = acc[mf][nf][0] + bb.x;
            v0.y = acc[mf][nf][1] + bb.y;
            v1.x = acc[mf][nf][2] + bb.x;
            v1.y = acc[mf][nf][3] + bb.y;
            if (MODE == 0) {
                int part = col >> 10;
                int h = (col >> 6) & (HEADS - 1);
                int d = col & 63;
                float* base = &g_qkv[(((size_t)part * HEADS + h) * NTOK) * HD + d];
                *(float2*)(base + (size_t)m0 * HD) = v0;
                *(float2*)(base + (size_t)(m0 + 8) * HD) = v1;
            } else {
                *(float2*)&Cout[(size_t)m0 * Nc + col] = v0;
                *(float2*)&Cout[(size_t)(m0 + 8) * Nc + col] = v1;
            }
        }
    }
}

// ---------------------------------------------------------------------------
// LayerNorm over D=64 on q (part 0) and k (part 1). One warp per vector.
// ---------------------------------------------------------------------------
__global__ void __launch_bounds__(256)
ln_kernel(const float* __restrict__ qg, const float* __restrict__ qb,
          const float* __restrict__ kg, const float* __restrict__ kb)
{
    const int NV = 2 * HEADS * NTOK;
    int warp = (blockIdx.x * blockDim.x + threadIdx.x) >> 5;
    int lane = threadIdx.x & 31;
    if (warp >= NV) return;

    float* v = g_qkv + (size_t)warp * HD;
    float2 x = *(float2*)&v[lane * 2];

    float s = x.x + x.y;
#pragma unroll
    for (int o = 16; o; o >>= 1) s += __shfl_xor_sync(0xffffffffu, s, o);
    float mu = s * (1.f / 64.f);

    float dx = x.x - mu, dy = x.y - mu;
    float ss = dx * dx + dy * dy;
#pragma unroll
    for (int o = 16; o; o >>= 1) ss += __shfl_xor_sync(0xffffffffu, ss, o);
    float rstd = rsqrtf(ss * (1.f / 64.f) + 1e-6f);

    bool isq = warp < HEADS * NTOK;
    const float* g = isq ? qg : kg;
    const float* b = isq ? qb : kb;
    x.x = dx * rstd * g[lane * 2] + b[lane * 2];
    x.y = dy * rstd * g[lane * 2 + 1] + b[lane * 2 + 1];
    *(float2*)&v[lane * 2] = x;
}

// ---------------------------------------------------------------------------
// Sparse attention v3 (unchanged from R3, WIN).
// ---------------------------------------------------------------------------
__global__ void __launch_bounds__(224, 2)
attn3_kernel(const int* __restrict__ gidx, const float* __restrict__ abias)
{
    extern __shared__ float sm[];
    float* Qs = sm;
    float* Ks = Qs + PTOK * RPAD;
    float* Vs = Ks + KT * RPAD;
    float* Ps = Vs + KT * RPAD;
    float* Bs = Ps + PTOK * PPAD;

    const int s = blockIdx.x;
    const int h = blockIdx.y;
    const int tid = threadIdx.x;
    const int tx = tid & 7;
    const int ty = tid >> 3;

    const float* qbuf = g_qkv + ((size_t)h * NTOK + (size_t)s * PTOK) * HD;
    const float* kbuf = g_qkv + (size_t)(HEADS + h) * NTOK * HD;
    const float* vbuf = g_qkv + (size_t)(2 * HEADS + h) * NTOK * HD;

    for (int i = tid; i < PTOK * 16; i += 224) {
        int q = i >> 4, c4 = i & 15;
        float4 v = ((const float4*)qbuf)[i];
        *(float4*)&Qs[q * RPAD + c4 * 4] = v;
    }

    float accO[7][8];
    float l[7];
#pragma unroll
    for (int i = 0; i < 7; i++) {
        l[i] = 0.f;
#pragma unroll
        for (int d = 0; d < 8; d++) accO[i][d] = 0.f;
    }

    const int gbase = s * MKV;

    for (int t = 0; t < NT; t++) {
        __syncthreads();
        const int t0 = t * KT;
        for (int i = tid; i < KT * 2 * 16; i += 224) {
            int row = i >> 4, c4 = i & 15;
            int key = row & (KT - 1);
            int gpos = t0 + key;
            int tok = gidx[gbase + (gpos < MKV ? gpos : 0)];
            const float* src = (row < KT ? kbuf : vbuf) + (size_t)tok * HD + c4 * 4;
            float* dst = (row < KT ? Ks : Vs) + key * RPAD + c4 * 4;
            *(float4*)dst = *(const float4*)src;
        }
        if (tid < KT) {
            int gpos = t0 + tid;
            Bs[tid] = (gpos < MKV) ? abias[gbase + gpos] - 10.f : -1e9f;
        }
        __syncthreads();

        float acc[7][4];
#pragma unroll
        for (int i = 0; i < 7; i++)
#pragma unroll
            for (int j = 0; j < 4; j++) acc[i][j] = 0.f;

#pragma unroll
        for (int kk = 0; kk < 16; kk++) {
            float4 kv[4];
#pragma unroll
            for (int j = 0; j < 4; j++)
                kv[j] = *(float4*)&Ks[(tx + 8 * j) * RPAD + kk * 4];
#pragma unroll
            for (int i = 0; i < 7; i++) {
                float4 qv = *(float4*)&Qs[(ty * 7 + i) * RPAD + kk * 4];
#pragma unroll
                for (int j = 0; j < 4; j++) {
                    acc[i][j] += qv.x * kv[j].x;
                    acc[i][j] += qv.y * kv[j].y;
                    acc[i][j] += qv.z * kv[j].z;
                    acc[i][j] += qv.w * kv[j].w;
                }
            }
        }

        float bj[4];
#pragma unroll
        for (int j = 0; j < 4; j++) bj[j] = Bs[tx + 8 * j];
#pragma unroll
        for (int i = 0; i < 7; i++) {
#pragma unroll
            for (int j = 0; j < 4; j++) {
                float p = __expf(fmaf(acc[i][j], 0.125f, bj[j]));
                l[i] += p;
                Ps[(ty * 7 + i) * PPAD + tx + 8 * j] = p;
            }
        }
        __syncthreads();

#pragma unroll 4
        for (int kk = 0; kk < KT; kk++) {
            float4 v0 = *(float4*)&Vs[kk * RPAD + tx * 8];
            float4 v1 = *(float4*)&Vs[kk * RPAD + tx * 8 + 4];
#pragma unroll
            for (int i = 0; i < 7; i++) {
                float p = Ps[(ty * 7 + i) * PPAD + kk];
                accO[i][0] += p * v0.x;
                accO[i][1] += p * v0.y;
                accO[i][2] += p * v0.z;
                accO[i][3] += p * v0.w;
                accO[i][4] += p * v1.x;
                accO[i][5] += p * v1.y;
                accO[i][6] += p * v1.z;
                accO[i][7] += p * v1.w;
            }
        }
    }

#pragma unroll
    for (int i = 0; i < 7; i++) {
        float v = l[i];
        v += __shfl_xor_sync(0xffffffffu, v, 1);
        v += __shfl_xor_sync(0xffffffffu, v, 2);
        v += __shfl_xor_sync(0xffffffffu, v, 4);
        l[i] = v;
    }

#pragma unroll
    for (int i = 0; i < 7; i++) {
        int q = ty * 7 + i;
        float inv = 1.f / l[i];
        float* op = g_att + (size_t)(s * PTOK + q) * CDIM + h * HD + tx * 8;
        float4 o0, o1;
        o0.x = accO[i][0] * inv; o0.y = accO[i][1] * inv;
        o0.z = accO[i][2] * inv; o0.w = accO[i][3] * inv;
        o1.x = accO[i][4] * inv; o1.y = accO[i][5] * inv;
        o1.z = accO[i][6] * inv; o1.w = accO[i][7] * inv;
        *(float4*)op = o0;
        *(float4*)(op + 4) = o1;
    }
}

// ---------------------------------------------------------------------------
extern "C" void kernel_launch(void* const* d_in, const int* in_sizes, int n_in,
                              void* d_out, int out_size)
{
    const float* x     = (const float*)d_in[0];
    const float* Wqkv  = (const float*)d_in[1];
    const float* bqkv  = (const float*)d_in[2];
    const float* qg    = (const float*)d_in[3];
    const float* qb    = (const float*)d_in[4];
    const float* kg    = (const float*)d_in[5];
    const float* kb    = (const float*)d_in[6];
    const float* Wproj = (const float*)d_in[7];
    const float* bproj = (const float*)d_in[8];
    const int*   gidx  = (const int*)d_in[9];
    const float* abias = (const float*)d_in[10];
    float* out = (float*)d_out;

    const int gemm_smem = 2 * STAGE_B;  // 49152
    const int attn_smem =
        (PTOK * RPAD + 2 * KT * RPAD + PTOK * PPAD + KT) * (int)sizeof(float);

    static int attr_set = 0;
    if (!attr_set) {
        cudaFuncSetAttribute(hmma_gemm_kernel<0>,
                             cudaFuncAttributeMaxDynamicSharedMemorySize, gemm_smem);
        cudaFuncSetAttribute(hmma_gemm_kernel<1>,
                             cudaFuncAttributeMaxDynamicSharedMemorySize, gemm_smem);
        cudaFuncSetAttribute(attn3_kernel,
                             cudaFuncAttributeMaxDynamicSharedMemorySize, attn_smem);
        attr_set = 1;
    }

    const int n4 = NTOK * KDIM / 4;

    // 0) prep: split x, transpose+split weights
    split_kernel<<<n4 / 256, 256>>>(x, n4);
    wsplit_kernel<0><<<dim3(NQKV / 32, KDIM / 32), 256>>>(Wqkv, NQKV);
    wsplit_kernel<1><<<dim3(1024 / 32, KDIM / 32), 256>>>(Wproj, 1024);

    // 1) QKV GEMM (HMMA): 6272 x 3072 x 1024, scatter epilogue into g_qkv
    hmma_gemm_kernel<0><<<dim3(NQKV / 128, NTOK / 128), 256, gemm_smem>>>(
        bqkv, nullptr, NQKV);

    // 2) LayerNorm q/k
    {
        int nvec = 2 * HEADS * NTOK;
        ln_kernel<<<(nvec * 32 + 255) / 256, 256>>>(qg, qb, kg, kb);
    }

    // 3) sparse attention
    attn3_kernel<<<dim3(SFR, HEADS), 224, attn_smem>>>(gidx, abias);

    // 4) split attention output, then proj GEMM (HMMA) -> d_out
    {
        float* attp;
        cudaGetSymbolAddress((void**)&attp, g_att);
        split_kernel<<<n4 / 256, 256>>>(attp, n4);
    }
    hmma_gemm_kernel<1><<<dim3(1024 / 128, NTOK / 128), 256, gemm_smem>>>(
        bproj, out, 1024);
}

// round 6
// speedup vs baseline: 3.5831x; 1.9009x over previous
#include <cuda_runtime.h>
#include <cuda_bf16.h>
#include <cstdint>

#define NTOK 6272
#define CDIM 1024
#define HEADS 16
#define HD 64
#define SFR 32
#define PTOK 196
#define MKV 1960
#define KT 32
#define NT 62          // 62*32 = 1984 >= 1960

#define KDIM 1024
#define NQKV 3072

// Scratch (no allocations anywhere)
__device__ float g_qkv[3u * HEADS * NTOK * HD];
__device__ __nv_bfloat16 g_ahi[(size_t)NTOK * KDIM];
__device__ __nv_bfloat16 g_alo[(size_t)NTOK * KDIM];
__device__ __nv_bfloat16 g_wqhi[(size_t)NQKV * KDIM];
__device__ __nv_bfloat16 g_wqlo[(size_t)NQKV * KDIM];
__device__ __nv_bfloat16 g_wphi[(size_t)1024 * KDIM];
__device__ __nv_bfloat16 g_wplo[(size_t)1024 * KDIM];
__device__ __nv_bfloat16 g_qhi[(size_t)HEADS * NTOK * HD];
__device__ __nv_bfloat16 g_qlo[(size_t)HEADS * NTOK * HD];
__device__ __nv_bfloat16 g_khi[(size_t)HEADS * NTOK * HD];
__device__ __nv_bfloat16 g_klo[(size_t)HEADS * NTOK * HD];
__device__ __nv_bfloat16 g_vhi[(size_t)HEADS * NTOK * HD];
__device__ __nv_bfloat16 g_vlo[(size_t)HEADS * NTOK * HD];

// ---------------------------------------------------------------------------
// helpers
// ---------------------------------------------------------------------------
__device__ __forceinline__ uint32_t smem_u32(const void* p) {
    uint32_t a;
    asm("{ .reg .u64 t; cvta.to.shared.u64 t, %1; cvt.u32.u64 %0, t; }"
        : "=r"(a) : "l"(p));
    return a;
}
__device__ __forceinline__ void ldsm4(uint32_t addr, uint32_t& r0, uint32_t& r1,
                                      uint32_t& r2, uint32_t& r3) {
    asm volatile("ldmatrix.sync.aligned.m8n8.x4.shared.b16 {%0,%1,%2,%3}, [%4];"
                 : "=r"(r0), "=r"(r1), "=r"(r2), "=r"(r3) : "r"(addr));
}
__device__ __forceinline__ void ldsm4t(uint32_t addr, uint32_t& r0, uint32_t& r1,
                                       uint32_t& r2, uint32_t& r3) {
    asm volatile("ldmatrix.sync.aligned.m8n8.x4.trans.shared.b16 {%0,%1,%2,%3}, [%4];"
                 : "=r"(r0), "=r"(r1), "=r"(r2), "=r"(r3) : "r"(addr));
}
__device__ __forceinline__ void mma_bf16(float& d0, float& d1, float& d2, float& d3,
                                         uint32_t a0, uint32_t a1, uint32_t a2, uint32_t a3,
                                         uint32_t b0, uint32_t b1) {
    asm volatile(
        "mma.sync.aligned.m16n8k16.row.col.f32.bf16.bf16.f32 "
        "{%0,%1,%2,%3}, {%4,%5,%6,%7}, {%8,%9}, {%0,%1,%2,%3};"
        : "+f"(d0), "+f"(d1), "+f"(d2), "+f"(d3)
        : "r"(a0), "r"(a1), "r"(a2), "r"(a3), "r"(b0), "r"(b1));
}
__device__ __forceinline__ uint32_t pack_bf16(float a, float b) {
    __nv_bfloat162 t;
    t.x = __float2bfloat16_rn(a);
    t.y = __float2bfloat16_rn(b);
    return *(uint32_t*)&t;
}

// ---------------------------------------------------------------------------
// Split fp32 -> bf16 hi/lo planes into g_ahi/g_alo (same layout)
// ---------------------------------------------------------------------------
__global__ void __launch_bounds__(256)
split_kernel(const float* __restrict__ src, int n4)
{
    int i = blockIdx.x * blockDim.x + threadIdx.x;
    if (i >= n4) return;
    float4 a = ((const float4*)src)[i];
    __nv_bfloat16 h0 = __float2bfloat16_rn(a.x);
    __nv_bfloat16 h1 = __float2bfloat16_rn(a.y);
    __nv_bfloat16 h2 = __float2bfloat16_rn(a.z);
    __nv_bfloat16 h3 = __float2bfloat16_rn(a.w);
    __nv_bfloat16 l0 = __float2bfloat16_rn(a.x - __bfloat162float(h0));
    __nv_bfloat16 l1 = __float2bfloat16_rn(a.y - __bfloat162float(h1));
    __nv_bfloat16 l2 = __float2bfloat16_rn(a.z - __bfloat162float(h2));
    __nv_bfloat16 l3 = __float2bfloat16_rn(a.w - __bfloat162float(h3));
    __nv_bfloat162 hh0; hh0.x = h0; hh0.y = h1;
    __nv_bfloat162 hh1; hh1.x = h2; hh1.y = h3;
    __nv_bfloat162 ll0; ll0.x = l0; ll0.y = l1;
    __nv_bfloat162 ll1; ll1.x = l2; ll1.y = l3;
    ((__nv_bfloat162*)g_ahi)[i * 2]     = hh0;
    ((__nv_bfloat162*)g_ahi)[i * 2 + 1] = hh1;
    ((__nv_bfloat162*)g_alo)[i * 2]     = ll0;
    ((__nv_bfloat162*)g_alo)[i * 2 + 1] = ll1;
}

// ---------------------------------------------------------------------------
// Transpose + split: W [1024][N] fp32 -> hi/lo [N][1024] bf16
// ---------------------------------------------------------------------------
template <int WHICH>
__global__ void __launch_bounds__(256)
wsplit_kernel(const float* __restrict__ W, int N)
{
    __nv_bfloat16* hi = (WHICH == 0) ? g_wqhi : g_wphi;
    __nv_bfloat16* lo = (WHICH == 0) ? g_wqlo : g_wplo;
    __shared__ float t[32][33];
    int n0 = blockIdx.x * 32, k0 = blockIdx.y * 32;
    int tx = threadIdx.x & 31, ty = threadIdx.x >> 5;
#pragma unroll
    for (int r = 0; r < 4; r++)
        t[ty + r * 8][tx] = W[(size_t)(k0 + ty + r * 8) * N + n0 + tx];
    __syncthreads();
#pragma unroll
    for (int r = 0; r < 4; r++) {
        int n = ty + r * 8;
        float a = t[tx][n];
        __nv_bfloat16 h = __float2bfloat16_rn(a);
        __nv_bfloat16 l = __float2bfloat16_rn(a - __bfloat162float(h));
        size_t o = (size_t)(n0 + n) * KDIM + k0 + tx;
        hi[o] = h;
        lo[o] = l;
    }
}

// ---------------------------------------------------------------------------
// HMMA GEMM (unchanged from R5 WIN). CTA 128x128, 8 warps, double-buffered.
// ---------------------------------------------------------------------------
#define RSTR 24
#define TILE_E (128 * RSTR)
#define STAGE_E (4 * TILE_E)
#define STAGE_B (STAGE_E * 2)
#define OFF_AH 0
#define OFF_AL TILE_E
#define OFF_BH (2 * TILE_E)
#define OFF_BL (3 * TILE_E)

template <int MODE>
__global__ void __launch_bounds__(256)
hmma_gemm_kernel(const float* __restrict__ bias, float* __restrict__ Cout, int Nc)
{
    extern __shared__ __nv_bfloat16 smb[];
    const uint32_t su = smem_u32(smb);

    const __nv_bfloat16* Bhi = (MODE == 0) ? g_wqhi : g_wphi;
    const __nv_bfloat16* Blo = (MODE == 0) ? g_wqlo : g_wplo;

    const int tid = threadIdx.x;
    const int wid = tid >> 5;
    const int lane = tid & 31;
    const int wm = wid & 1;
    const int wn = wid >> 1;
    const int bm = blockIdx.y * 128;
    const int bn = blockIdx.x * 128;

    const int grow = tid >> 1;
    const int ghalf = tid & 1;
    const __nv_bfloat16* pAhi = g_ahi + (size_t)(bm + grow) * KDIM + ghalf * 8;
    const __nv_bfloat16* pAlo = g_alo + (size_t)(bm + grow) * KDIM + ghalf * 8;
    const __nv_bfloat16* pBhi = Bhi + (size_t)(bn + grow) * KDIM + ghalf * 8;
    const __nv_bfloat16* pBlo = Blo + (size_t)(bn + grow) * KDIM + ghalf * 8;
    const uint32_t sstore = (uint32_t)(grow * RSTR + ghalf * 8) * 2;

    const uint32_t aAddr = (uint32_t)((wm * 64 + (lane & 15)) * RSTR + (lane >> 4) * 8);
    const uint32_t bAddr = (uint32_t)((wn * 32 + (lane & 7) + ((lane >> 4) & 1) * 8) * RSTR
                                      + ((lane >> 3) & 1) * 8);

    float acc[4][4][4];
#pragma unroll
    for (int mf = 0; mf < 4; mf++)
#pragma unroll
        for (int nf = 0; nf < 4; nf++)
#pragma unroll
            for (int e = 0; e < 4; e++) acc[mf][nf][e] = 0.f;

    uint4 rah = *(const uint4*)pAhi;
    uint4 ral = *(const uint4*)pAlo;
    uint4 rbh = *(const uint4*)pBhi;
    uint4 rbl = *(const uint4*)pBlo;
    {
        char* s0 = (char*)smb;
        *(uint4*)(s0 + OFF_AH * 2 + sstore) = rah;
        *(uint4*)(s0 + OFF_AL * 2 + sstore) = ral;
        *(uint4*)(s0 + OFF_BH * 2 + sstore) = rbh;
        *(uint4*)(s0 + OFF_BL * 2 + sstore) = rbl;
    }
    __syncthreads();

    const int NCHUNK = KDIM / 16;
    for (int c = 0; c < NCHUNK; c++) {
        if (c + 1 < NCHUNK) {
            int ko = (c + 1) * 16;
            rah = *(const uint4*)(pAhi + ko);
            ral = *(const uint4*)(pAlo + ko);
            rbh = *(const uint4*)(pBhi + ko);
            rbl = *(const uint4*)(pBlo + ko);
        }

        const uint32_t sb = su + (uint32_t)(c & 1) * STAGE_B;
        uint32_t bh[8], bl[8];
        ldsm4(sb + (OFF_BH + bAddr) * 2, bh[0], bh[1], bh[2], bh[3]);
        ldsm4(sb + (OFF_BH + bAddr + 16 * RSTR) * 2, bh[4], bh[5], bh[6], bh[7]);
        ldsm4(sb + (OFF_BL + bAddr) * 2, bl[0], bl[1], bl[2], bl[3]);
        ldsm4(sb + (OFF_BL + bAddr + 16 * RSTR) * 2, bl[4], bl[5], bl[6], bl[7]);

#pragma unroll
        for (int mf = 0; mf < 4; mf++) {
            uint32_t a0, a1, a2, a3;
            ldsm4(sb + (OFF_AH + aAddr + mf * 16 * RSTR) * 2, a0, a1, a2, a3);
#pragma unroll
            for (int nf = 0; nf < 4; nf++)
                mma_bf16(acc[mf][nf][0], acc[mf][nf][1], acc[mf][nf][2], acc[mf][nf][3],
                         a0, a1, a2, a3, bh[nf * 2], bh[nf * 2 + 1]);
#pragma unroll
            for (int nf = 0; nf < 4; nf++)
                mma_bf16(acc[mf][nf][0], acc[mf][nf][1], acc[mf][nf][2], acc[mf][nf][3],
                         a0, a1, a2, a3, bl[nf * 2], bl[nf * 2 + 1]);
            ldsm4(sb + (OFF_AL + aAddr + mf * 16 * RSTR) * 2, a0, a1, a2, a3);
#pragma unroll
            for (int nf = 0; nf < 4; nf++)
                mma_bf16(acc[mf][nf][0], acc[mf][nf][1], acc[mf][nf][2], acc[mf][nf][3],
                         a0, a1, a2, a3, bh[nf * 2], bh[nf * 2 + 1]);
        }

        if (c + 1 < NCHUNK) {
            char* sd = (char*)smb + ((c + 1) & 1) * STAGE_B;
            *(uint4*)(sd + OFF_AH * 2 + sstore) = rah;
            *(uint4*)(sd + OFF_AL * 2 + sstore) = ral;
            *(uint4*)(sd + OFF_BH * 2 + sstore) = rbh;
            *(uint4*)(sd + OFF_BL * 2 + sstore) = rbl;
        }
        __syncthreads();
    }

#pragma unroll
    for (int mf = 0; mf < 4; mf++) {
#pragma unroll
        for (int nf = 0; nf < 4; nf++) {
            int m0 = bm + wm * 64 + mf * 16 + (lane >> 2);
            int col = bn + wn * 32 + nf * 8 + (lane & 3) * 2;
            float2 bb = *(const float2*)&bias[col];
            float2 v0, v1;
            v0.x = acc[mf][nf][0] + bb.x;
            v0.y = acc[mf][nf][1] + bb.y;
            v1.x = acc[mf][nf][2] + bb.x;
            v1.y = acc[mf][nf][3] + bb.y;
            if (MODE == 0) {
                int part = col >> 10;
                int h = (col >> 6) & (HEADS - 1);
                int d = col & 63;
                float* base = &g_qkv[(((size_t)part * HEADS + h) * NTOK) * HD + d];
                *(float2*)(base + (size_t)m0 * HD) = v0;
                *(float2*)(base + (size_t)(m0 + 8) * HD) = v1;
            } else {
                *(float2*)&Cout[(size_t)m0 * Nc + col] = v0;
                *(float2*)&Cout[(size_t)(m0 + 8) * Nc + col] = v1;
            }
        }
    }
}

// ---------------------------------------------------------------------------
// LayerNorm + bf16 hi/lo split of q, k, and passthrough split of v.
// One warp per (part, head, token) vector of 64.
// ---------------------------------------------------------------------------
__global__ void __launch_bounds__(256)
ln2_kernel(const float* __restrict__ qg, const float* __restrict__ qb,
           const float* __restrict__ kg, const float* __restrict__ kb)
{
    const int HN = HEADS * NTOK;
    int warp = (blockIdx.x * blockDim.x + threadIdx.x) >> 5;
    int lane = threadIdx.x & 31;
    if (warp >= 3 * HN) return;

    const float* v = g_qkv + (size_t)warp * HD;
    float2 x = *(const float2*)&v[lane * 2];
    int part = warp / HN;
    int local = warp - part * HN;

    if (part < 2) {
        float s = x.x + x.y;
#pragma unroll
        for (int o = 16; o; o >>= 1) s += __shfl_xor_sync(0xffffffffu, s, o);
        float mu = s * (1.f / 64.f);
        float dx = x.x - mu, dy = x.y - mu;
        float ss = dx * dx + dy * dy;
#pragma unroll
        for (int o = 16; o; o >>= 1) ss += __shfl_xor_sync(0xffffffffu, ss, o);
        float rstd = rsqrtf(ss * (1.f / 64.f) + 1e-6f);
        const float* g = (part == 0) ? qg : kg;
        const float* b = (part == 0) ? qb : kb;
        x.x = dx * rstd * g[lane * 2] + b[lane * 2];
        x.y = dy * rstd * g[lane * 2 + 1] + b[lane * 2 + 1];
    }

    __nv_bfloat16* hi = (part == 0) ? g_qhi : (part == 1) ? g_khi : g_vhi;
    __nv_bfloat16* lo = (part == 0) ? g_qlo : (part == 1) ? g_klo : g_vlo;
    __nv_bfloat16 h0 = __float2bfloat16_rn(x.x);
    __nv_bfloat16 h1 = __float2bfloat16_rn(x.y);
    __nv_bfloat16 l0 = __float2bfloat16_rn(x.x - __bfloat162float(h0));
    __nv_bfloat16 l1 = __float2bfloat16_rn(x.y - __bfloat162float(h1));
    __nv_bfloat162 ph; ph.x = h0; ph.y = h1;
    __nv_bfloat162 pl; pl.x = l0; pl.y = l1;
    *(__nv_bfloat162*)&hi[(size_t)local * HD + lane * 2] = ph;
    *(__nv_bfloat162*)&lo[(size_t)local * HD + lane * 2] = pl;
}

// ---------------------------------------------------------------------------
// HMMA flash attention. Block = (s, h). 7 warps x 32 query rows (224 >= 196).
// QK: 3-product bf16 split; softmax with static max 10; PV: 3-product split.
// Writes bf16 hi/lo output directly into g_ahi/g_alo [token][1024].
// ---------------------------------------------------------------------------
#define AST 72                       // smem row stride (bf16 elems) = 144B
#define QLO_ELEMS (224 * AST)        // 16128
#define KARR (KT * AST)              // 2304
#define TILE_OFF QLO_ELEMS
#define BIAS_OFF (QLO_ELEMS + 4 * KARR)   // 25344 elems
#define AT_SMEM_BYTES (BIAS_OFF * 2 + KT * 4 + 16)

__global__ void __launch_bounds__(224, 1)
attn4_kernel(const int* __restrict__ gidx, const float* __restrict__ abias)
{
    extern __shared__ __nv_bfloat16 smb2[];
    __nv_bfloat16* Qlo = smb2;
    __nv_bfloat16* Tile = smb2 + TILE_OFF;      // [khi|klo|vhi|vlo][32][72]
    float* Bs = (float*)(smb2 + BIAS_OFF);
    const uint32_t su = smem_u32(smb2);

    const int s = blockIdx.x, h = blockIdx.y;
    const int tid = threadIdx.x, wid = tid >> 5, lane = tid & 31;
    const int m0 = wid * 32;

    const __nv_bfloat16* qh  = g_qhi + ((size_t)h * NTOK + (size_t)s * PTOK) * HD;
    const __nv_bfloat16* qlg = g_qlo + ((size_t)h * NTOK + (size_t)s * PTOK) * HD;
    const __nv_bfloat16* kh = g_khi + (size_t)h * NTOK * HD;
    const __nv_bfloat16* kl = g_klo + (size_t)h * NTOK * HD;
    const __nv_bfloat16* vh = g_vhi + (size_t)h * NTOK * HD;
    const __nv_bfloat16* vl = g_vlo + (size_t)h * NTOK * HD;

    // Qlo -> smem (row per thread, clamp rows >= 196)
    {
        int row = tid;
        int srcr = row < PTOK ? row : PTOK - 1;
        const uint4* p = (const uint4*)(qlg + (size_t)srcr * HD);
#pragma unroll
        for (int j = 0; j < 8; j++)
            *(uint4*)&Qlo[row * AST + j * 8] = p[j];
    }

    // Qhi fragments in registers (direct global loads in mma A-frag layout)
    uint32_t qf[2][4][4];
    {
        int r = lane >> 2, c2 = (lane & 3) * 2;
#pragma unroll
        for (int mf = 0; mf < 2; mf++) {
            int r0 = m0 + mf * 16 + r;
            int r1 = r0 + 8;
            if (r0 > PTOK - 1) r0 = PTOK - 1;
            if (r1 > PTOK - 1) r1 = PTOK - 1;
#pragma unroll
            for (int kf = 0; kf < 4; kf++) {
                int c0 = kf * 16 + c2;
                qf[mf][kf][0] = *(const uint32_t*)(qh + (size_t)r0 * HD + c0);
                qf[mf][kf][1] = *(const uint32_t*)(qh + (size_t)r1 * HD + c0);
                qf[mf][kf][2] = *(const uint32_t*)(qh + (size_t)r0 * HD + c0 + 8);
                qf[mf][kf][3] = *(const uint32_t*)(qh + (size_t)r1 * HD + c0 + 8);
            }
        }
    }

    float o[2][8][4];
    float lsum[2][2];
#pragma unroll
    for (int mf = 0; mf < 2; mf++) {
        lsum[mf][0] = 0.f; lsum[mf][1] = 0.f;
#pragma unroll
        for (int nf = 0; nf < 8; nf++)
#pragma unroll
            for (int e = 0; e < 4; e++) o[mf][nf][e] = 0.f;
    }

    const int gbase = s * MKV;

    // ldsm base addresses (bytes)
    const uint32_t kaddr = su + 2 * (TILE_OFF
        + ((lane & 7) + ((lane >> 4) & 1) * 8) * AST + ((lane >> 3) & 1) * 8);
    const uint32_t vaddr = su + 2 * (TILE_OFF + 2 * KARR
        + ((lane & 7) + ((lane >> 3) & 1) * 8) * AST + ((lane >> 4) & 1) * 8);
    const uint32_t qladdr = su + 2 * ((m0 + (lane & 15)) * AST + (lane >> 4) * 8);

    // prefetch tile 0
    uint4 pf[5];
    float pbias = 0.f;
#pragma unroll
    for (int it = 0; it < 5; it++) {
        int slot = tid + it * 224;
        if (slot < 1024) {
            int a = slot >> 8, r = (slot >> 3) & 31, seg = slot & 7;
            int gpos = r;   // tile 0
            int tok = gidx[gbase + (gpos < MKV ? gpos : 0)];
            const __nv_bfloat16* bp = (a == 0) ? kh : (a == 1) ? kl : (a == 2) ? vh : vl;
            pf[it] = *(const uint4*)(bp + (size_t)tok * HD + seg * 8);
        }
    }
    if (tid < KT) pbias = (tid < MKV) ? abias[gbase + tid] - 10.f : -1e9f;

    for (int t = 0; t < NT; t++) {
        __syncthreads();
#pragma unroll
        for (int it = 0; it < 5; it++) {
            int slot = tid + it * 224;
            if (slot < 1024) {
                int a = slot >> 8, r = (slot >> 3) & 31, seg = slot & 7;
                *(uint4*)&Tile[a * KARR + r * AST + seg * 8] = pf[it];
            }
        }
        if (tid < KT) Bs[tid] = pbias;
        __syncthreads();

        if (t + 1 < NT) {
            int t0n = (t + 1) * KT;
#pragma unroll
            for (int it = 0; it < 5; it++) {
                int slot = tid + it * 224;
                if (slot < 1024) {
                    int a = slot >> 8, r = (slot >> 3) & 31, seg = slot & 7;
                    int gpos = t0n + r;
                    int tok = gidx[gbase + (gpos < MKV ? gpos : 0)];
                    const __nv_bfloat16* bp = (a == 0) ? kh : (a == 1) ? kl : (a == 2) ? vh : vl;
                    pf[it] = *(const uint4*)(bp + (size_t)tok * HD + seg * 8);
                }
            }
            if (tid < KT) {
                int gp = t0n + tid;
                pbias = (gp < MKV) ? abias[gbase + gp] - 10.f : -1e9f;
            }
        }

        // ---- QK: 3-product bf16 split ----
        float sc[2][4][4];
#pragma unroll
        for (int mf = 0; mf < 2; mf++)
#pragma unroll
            for (int nf = 0; nf < 4; nf++)
#pragma unroll
                for (int e = 0; e < 4; e++) sc[mf][nf][e] = 0.f;

#pragma unroll
        for (int kf = 0; kf < 4; kf++) {
            uint32_t bh0[4], bh1[4], bl0[4], bl1[4];
            ldsm4(kaddr + kf * 32, bh0[0], bh0[1], bh0[2], bh0[3]);
            ldsm4(kaddr + kf * 32 + 16 * AST * 2, bh1[0], bh1[1], bh1[2], bh1[3]);
            ldsm4(kaddr + KARR * 2 + kf * 32, bl0[0], bl0[1], bl0[2], bl0[3]);
            ldsm4(kaddr + KARR * 2 + kf * 32 + 16 * AST * 2, bl1[0], bl1[1], bl1[2], bl1[3]);
#pragma unroll
            for (int mf = 0; mf < 2; mf++) {
                uint32_t q0 = qf[mf][kf][0], q1 = qf[mf][kf][1];
                uint32_t q2 = qf[mf][kf][2], q3 = qf[mf][kf][3];
                mma_bf16(sc[mf][0][0], sc[mf][0][1], sc[mf][0][2], sc[mf][0][3],
                         q0, q1, q2, q3, bh0[0], bh0[1]);
                mma_bf16(sc[mf][1][0], sc[mf][1][1], sc[mf][1][2], sc[mf][1][3],
                         q0, q1, q2, q3, bh0[2], bh0[3]);
                mma_bf16(sc[mf][2][0], sc[mf][2][1], sc[mf][2][2], sc[mf][2][3],
                         q0, q1, q2, q3, bh1[0], bh1[1]);
                mma_bf16(sc[mf][3][0], sc[mf][3][1], sc[mf][3][2], sc[mf][3][3],
                         q0, q1, q2, q3, bh1[2], bh1[3]);
                mma_bf16(sc[mf][0][0], sc[mf][0][1], sc[mf][0][2], sc[mf][0][3],
                         q0, q1, q2, q3, bl0[0], bl0[1]);
                mma_bf16(sc[mf][1][0], sc[mf][1][1], sc[mf][1][2], sc[mf][1][3],
                         q0, q1, q2, q3, bl0[2], bl0[3]);
                mma_bf16(sc[mf][2][0], sc[mf][2][1], sc[mf][2][2], sc[mf][2][3],
                         q0, q1, q2, q3, bl1[0], bl1[1]);
                mma_bf16(sc[mf][3][0], sc[mf][3][1], sc[mf][3][2], sc[mf][3][3],
                         q0, q1, q2, q3, bl1[2], bl1[3]);
                uint32_t ql0, ql1, ql2, ql3;
                ldsm4(qladdr + mf * 16 * AST * 2 + kf * 32, ql0, ql1, ql2, ql3);
                mma_bf16(sc[mf][0][0], sc[mf][0][1], sc[mf][0][2], sc[mf][0][3],
                         ql0, ql1, ql2, ql3, bh0[0], bh0[1]);
                mma_bf16(sc[mf][1][0], sc[mf][1][1], sc[mf][1][2], sc[mf][1][3],
                         ql0, ql1, ql2, ql3, bh0[2], bh0[3]);
                mma_bf16(sc[mf][2][0], sc[mf][2][1], sc[mf][2][2], sc[mf][2][3],
                         ql0, ql1, ql2, ql3, bh1[0], bh1[1]);
                mma_bf16(sc[mf][3][0], sc[mf][3][1], sc[mf][3][2], sc[mf][3][3],
                         ql0, ql1, ql2, ql3, bh1[2], bh1[3]);
            }
        }

        // ---- softmax weights (static max folded into Bs) + P split ----
        uint32_t phi[2][2][4], plo[2][2][4];
#pragma unroll
        for (int mf = 0; mf < 2; mf++) {
#pragma unroll
            for (int nf = 0; nf < 4; nf++) {
                float2 bb = *(const float2*)&Bs[nf * 8 + (lane & 3) * 2];
                float p0 = __expf(fmaf(sc[mf][nf][0], 0.125f, bb.x));
                float p1 = __expf(fmaf(sc[mf][nf][1], 0.125f, bb.y));
                float p2 = __expf(fmaf(sc[mf][nf][2], 0.125f, bb.x));
                float p3 = __expf(fmaf(sc[mf][nf][3], 0.125f, bb.y));
                lsum[mf][0] += p0 + p1;
                lsum[mf][1] += p2 + p3;
                uint32_t h01 = pack_bf16(p0, p1);
                uint32_t h23 = pack_bf16(p2, p3);
                __nv_bfloat162 hv01 = *(__nv_bfloat162*)&h01;
                __nv_bfloat162 hv23 = *(__nv_bfloat162*)&h23;
                uint32_t l01 = pack_bf16(p0 - __bfloat162float(hv01.x),
                                         p1 - __bfloat162float(hv01.y));
                uint32_t l23 = pack_bf16(p2 - __bfloat162float(hv23.x),
                                         p3 - __bfloat162float(hv23.y));
                int kf2 = nf >> 1, hf = (nf & 1) * 2;
                phi[mf][kf2][hf] = h01; phi[mf][kf2][hf + 1] = h23;
                plo[mf][kf2][hf] = l01; plo[mf][kf2][hf + 1] = l23;
            }
        }

        // ---- PV: 3-product split, V via ldsm.trans ----
#pragma unroll
        for (int kf = 0; kf < 2; kf++) {
            uint32_t vhf[16], vlf[16];
#pragma unroll
            for (int db = 0; db < 4; db++) {
                ldsm4t(vaddr + kf * (16 * AST * 2) + db * 32,
                       vhf[db * 4], vhf[db * 4 + 1], vhf[db * 4 + 2], vhf[db * 4 + 3]);
                ldsm4t(vaddr + KARR * 2 + kf * (16 * AST * 2) + db * 32,
                       vlf[db * 4], vlf[db * 4 + 1], vlf[db * 4 + 2], vlf[db * 4 + 3]);
            }
#pragma unroll
            for (int mf = 0; mf < 2; mf++) {
#pragma unroll
                for (int nfd = 0; nfd < 8; nfd++) {
                    int vi = (nfd >> 1) * 4 + (nfd & 1) * 2;
                    mma_bf16(o[mf][nfd][0], o[mf][nfd][1], o[mf][nfd][2], o[mf][nfd][3],
                             phi[mf][kf][0], phi[mf][kf][1], phi[mf][kf][2], phi[mf][kf][3],
                             vhf[vi], vhf[vi + 1]);
                    mma_bf16(o[mf][nfd][0], o[mf][nfd][1], o[mf][nfd][2], o[mf][nfd][3],
                             phi[mf][kf][0], phi[mf][kf][1], phi[mf][kf][2], phi[mf][kf][3],
                             vlf[vi], vlf[vi + 1]);
                    mma_bf16(o[mf][nfd][0], o[mf][nfd][1], o[mf][nfd][2], o[mf][nfd][3],
                             plo[mf][kf][0], plo[mf][kf][1], plo[mf][kf][2], plo[mf][kf][3],
                             vhf[vi], vhf[vi + 1]);
                }
            }
        }
    }

    // reduce l over the 4 lanes sharing each row
#pragma unroll
    for (int mf = 0; mf < 2; mf++) {
#pragma unroll
        for (int j = 0; j < 2; j++) {
            float v = lsum[mf][j];
            v += __shfl_xor_sync(0xffffffffu, v, 1);
            v += __shfl_xor_sync(0xffffffffu, v, 2);
            lsum[mf][j] = v;
        }
    }

    // epilogue: divide, split to bf16 hi/lo, write g_ahi/g_alo [token][1024]
    {
        int r = lane >> 2, c2 = (lane & 3) * 2;
#pragma unroll
        for (int mf = 0; mf < 2; mf++) {
            int rowq0 = m0 + mf * 16 + r;
            int rowq1 = rowq0 + 8;
            float i0 = 1.f / lsum[mf][0];
            float i1 = 1.f / lsum[mf][1];
            if (rowq0 < PTOK) {
                size_t base = (size_t)(s * PTOK + rowq0) * CDIM + h * HD + c2;
#pragma unroll
                for (int nfd = 0; nfd < 8; nfd++) {
                    float f0 = o[mf][nfd][0] * i0;
                    float f1 = o[mf][nfd][1] * i0;
                    uint32_t hp = pack_bf16(f0, f1);
                    __nv_bfloat162 hv = *(__nv_bfloat162*)&hp;
                    uint32_t lp = pack_bf16(f0 - __bfloat162float(hv.x),
                                            f1 - __bfloat162float(hv.y));
                    *(uint32_t*)&g_ahi[base + nfd * 8] = hp;
                    *(uint32_t*)&g_alo[base + nfd * 8] = lp;
                }
            }
            if (rowq1 < PTOK) {
                size_t base = (size_t)(s * PTOK + rowq1) * CDIM + h * HD + c2;
#pragma unroll
                for (int nfd = 0; nfd < 8; nfd++) {
                    float f0 = o[mf][nfd][2] * i1;
                    float f1 = o[mf][nfd][3] * i1;
                    uint32_t hp = pack_bf16(f0, f1);
                    __nv_bfloat162 hv = *(__nv_bfloat162*)&hp;
                    uint32_t lp = pack_bf16(f0 - __bfloat162float(hv.x),
                                            f1 - __bfloat162float(hv.y));
                    *(uint32_t*)&g_ahi[base + nfd * 8] = hp;
                    *(uint32_t*)&g_alo[base + nfd * 8] = lp;
                }
            }
        }
    }
}

// ---------------------------------------------------------------------------
extern "C" void kernel_launch(void* const* d_in, const int* in_sizes, int n_in,
                              void* d_out, int out_size)
{
    const float* x     = (const float*)d_in[0];
    const float* Wqkv  = (const float*)d_in[1];
    const float* bqkv  = (const float*)d_in[2];
    const float* qg    = (const float*)d_in[3];
    const float* qb    = (const float*)d_in[4];
    const float* kg    = (const float*)d_in[5];
    const float* kb    = (const float*)d_in[6];
    const float* Wproj = (const float*)d_in[7];
    const float* bproj = (const float*)d_in[8];
    const int*   gidx  = (const int*)d_in[9];
    const float* abias = (const float*)d_in[10];
    float* out = (float*)d_out;

    const int gemm_smem = 2 * STAGE_B;

    static int attr_set = 0;
    if (!attr_set) {
        cudaFuncSetAttribute(hmma_gemm_kernel<0>,
                             cudaFuncAttributeMaxDynamicSharedMemorySize, gemm_smem);
        cudaFuncSetAttribute(hmma_gemm_kernel<1>,
                             cudaFuncAttributeMaxDynamicSharedMemorySize, gemm_smem);
        cudaFuncSetAttribute(attn4_kernel,
                             cudaFuncAttributeMaxDynamicSharedMemorySize, AT_SMEM_BYTES);
        attr_set = 1;
    }

    const int n4 = NTOK * KDIM / 4;

    // 0) prep: split x, transpose+split weights
    split_kernel<<<n4 / 256, 256>>>(x, n4);
    wsplit_kernel<0><<<dim3(NQKV / 32, KDIM / 32), 256>>>(Wqkv, NQKV);
    wsplit_kernel<1><<<dim3(1024 / 32, KDIM / 32), 256>>>(Wproj, 1024);

    // 1) QKV GEMM (HMMA) -> g_qkv fp32
    hmma_gemm_kernel<0><<<dim3(NQKV / 128, NTOK / 128), 256, gemm_smem>>>(
        bqkv, nullptr, NQKV);

    // 2) LayerNorm + bf16 hi/lo split of q/k/v
    {
        int nvec = 3 * HEADS * NTOK;
        ln2_kernel<<<(nvec * 32 + 255) / 256, 256>>>(qg, qb, kg, kb);
    }

    // 3) HMMA flash attention -> writes g_ahi/g_alo directly
    attn4_kernel<<<dim3(SFR, HEADS), 224, AT_SMEM_BYTES>>>(gidx, abias);

    // 4) proj GEMM (HMMA) -> d_out
    hmma_gemm_kernel<1><<<dim3(1024 / 128, NTOK / 128), 256, gemm_smem>>>(
        bproj, out, 1024);
}

// round 7
// speedup vs baseline: 3.8771x; 1.0821x over previous
#include <cuda_runtime.h>
#include <cuda_bf16.h>
#include <cstdint>

#define NTOK 6272
#define CDIM 1024
#define HEADS 16
#define HD 64
#define SFR 32
#define PTOK 196
#define MKV 1960
#define KT 32
#define NT 62          // 62*32 = 1984 >= 1960

#define KDIM 1024
#define NQKV 3072

// Scratch (no allocations anywhere)
__device__ float g_qkv[3u * HEADS * NTOK * HD];
__device__ __nv_bfloat16 g_ahi[(size_t)NTOK * KDIM];
__device__ __nv_bfloat16 g_alo[(size_t)NTOK * KDIM];
__device__ __nv_bfloat16 g_wqhi[(size_t)NQKV * KDIM];
__device__ __nv_bfloat16 g_wqlo[(size_t)NQKV * KDIM];
__device__ __nv_bfloat16 g_wphi[(size_t)1024 * KDIM];
__device__ __nv_bfloat16 g_wplo[(size_t)1024 * KDIM];
__device__ __nv_bfloat16 g_qhi[(size_t)HEADS * NTOK * HD];
__device__ __nv_bfloat16 g_qlo[(size_t)HEADS * NTOK * HD];
__device__ __nv_bfloat16 g_khi[(size_t)HEADS * NTOK * HD];
__device__ __nv_bfloat16 g_klo[(size_t)HEADS * NTOK * HD];
__device__ __nv_bfloat16 g_vhi[(size_t)HEADS * NTOK * HD];
__device__ __nv_bfloat16 g_vlo[(size_t)HEADS * NTOK * HD];

// ---------------------------------------------------------------------------
// helpers
// ---------------------------------------------------------------------------
__device__ __forceinline__ uint32_t smem_u32(const void* p) {
    uint32_t a;
    asm("{ .reg .u64 t; cvta.to.shared.u64 t, %1; cvt.u32.u64 %0, t; }"
        : "=r"(a) : "l"(p));
    return a;
}
__device__ __forceinline__ void ldsm4(uint32_t addr, uint32_t& r0, uint32_t& r1,
                                      uint32_t& r2, uint32_t& r3) {
    asm volatile("ldmatrix.sync.aligned.m8n8.x4.shared.b16 {%0,%1,%2,%3}, [%4];"
                 : "=r"(r0), "=r"(r1), "=r"(r2), "=r"(r3) : "r"(addr));
}
__device__ __forceinline__ void ldsm4t(uint32_t addr, uint32_t& r0, uint32_t& r1,
                                       uint32_t& r2, uint32_t& r3) {
    asm volatile("ldmatrix.sync.aligned.m8n8.x4.trans.shared.b16 {%0,%1,%2,%3}, [%4];"
                 : "=r"(r0), "=r"(r1), "=r"(r2), "=r"(r3) : "r"(addr));
}
__device__ __forceinline__ void mma_bf16(float& d0, float& d1, float& d2, float& d3,
                                         uint32_t a0, uint32_t a1, uint32_t a2, uint32_t a3,
                                         uint32_t b0, uint32_t b1) {
    asm volatile(
        "mma.sync.aligned.m16n8k16.row.col.f32.bf16.bf16.f32 "
        "{%0,%1,%2,%3}, {%4,%5,%6,%7}, {%8,%9}, {%0,%1,%2,%3};"
        : "+f"(d0), "+f"(d1), "+f"(d2), "+f"(d3)
        : "r"(a0), "r"(a1), "r"(a2), "r"(a3), "r"(b0), "r"(b1));
}
__device__ __forceinline__ uint32_t pack_bf16(float a, float b) {
    __nv_bfloat162 t;
    t.x = __float2bfloat16_rn(a);
    t.y = __float2bfloat16_rn(b);
    return *(uint32_t*)&t;
}
__device__ __forceinline__ void cpa16(uint32_t dst, const void* src) {
    asm volatile("cp.async.cg.shared.global [%0], [%1], 16;"
                 :: "r"(dst), "l"(src) : "memory");
}
__device__ __forceinline__ void cpa_commit() {
    asm volatile("cp.async.commit_group;" ::: "memory");
}
__device__ __forceinline__ void cpa_wait1() {
    asm volatile("cp.async.wait_group 1;" ::: "memory");
}

// ---------------------------------------------------------------------------
// Split fp32 -> bf16 hi/lo planes into g_ahi/g_alo (same layout)
// ---------------------------------------------------------------------------
__global__ void __launch_bounds__(256)
split_kernel(const float* __restrict__ src, int n4)
{
    int i = blockIdx.x * blockDim.x + threadIdx.x;
    if (i >= n4) return;
    float4 a = ((const float4*)src)[i];
    __nv_bfloat16 h0 = __float2bfloat16_rn(a.x);
    __nv_bfloat16 h1 = __float2bfloat16_rn(a.y);
    __nv_bfloat16 h2 = __float2bfloat16_rn(a.z);
    __nv_bfloat16 h3 = __float2bfloat16_rn(a.w);
    __nv_bfloat16 l0 = __float2bfloat16_rn(a.x - __bfloat162float(h0));
    __nv_bfloat16 l1 = __float2bfloat16_rn(a.y - __bfloat162float(h1));
    __nv_bfloat16 l2 = __float2bfloat16_rn(a.z - __bfloat162float(h2));
    __nv_bfloat16 l3 = __float2bfloat16_rn(a.w - __bfloat162float(h3));
    __nv_bfloat162 hh0; hh0.x = h0; hh0.y = h1;
    __nv_bfloat162 hh1; hh1.x = h2; hh1.y = h3;
    __nv_bfloat162 ll0; ll0.x = l0; ll0.y = l1;
    __nv_bfloat162 ll1; ll1.x = l2; ll1.y = l3;
    ((__nv_bfloat162*)g_ahi)[i * 2]     = hh0;
    ((__nv_bfloat162*)g_ahi)[i * 2 + 1] = hh1;
    ((__nv_bfloat162*)g_alo)[i * 2]     = ll0;
    ((__nv_bfloat162*)g_alo)[i * 2 + 1] = ll1;
}

// ---------------------------------------------------------------------------
// Transpose + split: W [1024][N] fp32 -> hi/lo [N][1024] bf16
// ---------------------------------------------------------------------------
template <int WHICH>
__global__ void __launch_bounds__(256)
wsplit_kernel(const float* __restrict__ W, int N)
{
    __nv_bfloat16* hi = (WHICH == 0) ? g_wqhi : g_wphi;
    __nv_bfloat16* lo = (WHICH == 0) ? g_wqlo : g_wplo;
    __shared__ float t[32][33];
    int n0 = blockIdx.x * 32, k0 = blockIdx.y * 32;
    int tx = threadIdx.x & 31, ty = threadIdx.x >> 5;
#pragma unroll
    for (int r = 0; r < 4; r++)
        t[ty + r * 8][tx] = W[(size_t)(k0 + ty + r * 8) * N + n0 + tx];
    __syncthreads();
#pragma unroll
    for (int r = 0; r < 4; r++) {
        int n = ty + r * 8;
        float a = t[tx][n];
        __nv_bfloat16 h = __float2bfloat16_rn(a);
        __nv_bfloat16 l = __float2bfloat16_rn(a - __bfloat162float(h));
        size_t o = (size_t)(n0 + n) * KDIM + k0 + tx;
        hi[o] = h;
        lo[o] = l;
    }
}

// ---------------------------------------------------------------------------
// HMMA GEMM v2: cp.async 3-stage pipeline, 2 CTAs/SM.
// CTA 128x128, 8 warps (64x32 each), k-chunk 16.
// D = Ahi*Bhi + Ahi*Blo + Alo*Bhi, fp32 accum.
// ---------------------------------------------------------------------------
#define RSTR 24
#define TILE_E (128 * RSTR)
#define STAGE_E (4 * TILE_E)
#define STAGE_B (STAGE_E * 2)          // 24576 bytes
#define NSTAGE 3
#define GEMM_SMEM (NSTAGE * STAGE_B)   // 73728 bytes
#define OFF_AH 0
#define OFF_AL TILE_E
#define OFF_BH (2 * TILE_E)
#define OFF_BL (3 * TILE_E)

template <int MODE>
__global__ void __launch_bounds__(256, 2)
hmma_gemm_kernel(const float* __restrict__ bias, float* __restrict__ Cout, int Nc)
{
    extern __shared__ __nv_bfloat16 smb[];
    const uint32_t su = smem_u32(smb);

    const __nv_bfloat16* Bhi = (MODE == 0) ? g_wqhi : g_wphi;
    const __nv_bfloat16* Blo = (MODE == 0) ? g_wqlo : g_wplo;

    const int tid = threadIdx.x;
    const int wid = tid >> 5;
    const int lane = tid & 31;
    const int wm = wid & 1;
    const int wn = wid >> 1;
    const int bm = blockIdx.y * 128;
    const int bn = blockIdx.x * 128;

    const int grow = tid >> 1;
    const int ghalf = tid & 1;
    const __nv_bfloat16* pAhi = g_ahi + (size_t)(bm + grow) * KDIM + ghalf * 8;
    const __nv_bfloat16* pAlo = g_alo + (size_t)(bm + grow) * KDIM + ghalf * 8;
    const __nv_bfloat16* pBhi = Bhi + (size_t)(bn + grow) * KDIM + ghalf * 8;
    const __nv_bfloat16* pBlo = Blo + (size_t)(bn + grow) * KDIM + ghalf * 8;
    const uint32_t sstore = (uint32_t)(grow * RSTR + ghalf * 8) * 2;   // bytes

    const uint32_t aAddr = (uint32_t)((wm * 64 + (lane & 15)) * RSTR + (lane >> 4) * 8) * 2;
    const uint32_t bAddr = (uint32_t)((wn * 32 + (lane & 7) + ((lane >> 4) & 1) * 8) * RSTR
                                      + ((lane >> 3) & 1) * 8) * 2;

    float acc[4][4][4];
#pragma unroll
    for (int mf = 0; mf < 4; mf++)
#pragma unroll
        for (int nf = 0; nf < 4; nf++)
#pragma unroll
            for (int e = 0; e < 4; e++) acc[mf][nf][e] = 0.f;

    const int NCHUNK = KDIM / 16;      // 64

    // prologue: issue chunks 0 and 1
#pragma unroll
    for (int c = 0; c < 2; c++) {
        uint32_t sb = su + (uint32_t)c * STAGE_B + sstore;
        int ko = c * 16;
        cpa16(sb + OFF_AH * 2, pAhi + ko);
        cpa16(sb + OFF_AL * 2, pAlo + ko);
        cpa16(sb + OFF_BH * 2, pBhi + ko);
        cpa16(sb + OFF_BL * 2, pBlo + ko);
        cpa_commit();
    }

    for (int c = 0; c < NCHUNK; c++) {
        cpa_wait1();                   // chunk c's copy complete
        __syncthreads();               // all warps done with slot (c+2)%3's prior data

        if (c + 2 < NCHUNK) {          // issue chunk c+2 into slot (c+2)%3
            int slot = (c + 2) % NSTAGE;
            uint32_t sb = su + (uint32_t)slot * STAGE_B + sstore;
            int ko = (c + 2) * 16;
            cpa16(sb + OFF_AH * 2, pAhi + ko);
            cpa16(sb + OFF_AL * 2, pAlo + ko);
            cpa16(sb + OFF_BH * 2, pBhi + ko);
            cpa16(sb + OFF_BL * 2, pBlo + ko);
        }
        cpa_commit();                  // (possibly empty) keeps group accounting uniform

        const uint32_t sb = su + (uint32_t)(c % NSTAGE) * STAGE_B;
        uint32_t bh[8], bl[8];
        ldsm4(sb + OFF_BH * 2 + bAddr, bh[0], bh[1], bh[2], bh[3]);
        ldsm4(sb + OFF_BH * 2 + bAddr + 16 * RSTR * 2, bh[4], bh[5], bh[6], bh[7]);
        ldsm4(sb + OFF_BL * 2 + bAddr, bl[0], bl[1], bl[2], bl[3]);
        ldsm4(sb + OFF_BL * 2 + bAddr + 16 * RSTR * 2, bl[4], bl[5], bl[6], bl[7]);

#pragma unroll
        for (int mf = 0; mf < 4; mf++) {
            uint32_t a0, a1, a2, a3;
            ldsm4(sb + OFF_AH * 2 + aAddr + mf * 16 * RSTR * 2, a0, a1, a2, a3);
#pragma unroll
            for (int nf = 0; nf < 4; nf++)
                mma_bf16(acc[mf][nf][0], acc[mf][nf][1], acc[mf][nf][2], acc[mf][nf][3],
                         a0, a1, a2, a3, bh[nf * 2], bh[nf * 2 + 1]);
#pragma unroll
            for (int nf = 0; nf < 4; nf++)
                mma_bf16(acc[mf][nf][0], acc[mf][nf][1], acc[mf][nf][2], acc[mf][nf][3],
                         a0, a1, a2, a3, bl[nf * 2], bl[nf * 2 + 1]);
            ldsm4(sb + OFF_AL * 2 + aAddr + mf * 16 * RSTR * 2, a0, a1, a2, a3);
#pragma unroll
            for (int nf = 0; nf < 4; nf++)
                mma_bf16(acc[mf][nf][0], acc[mf][nf][1], acc[mf][nf][2], acc[mf][nf][3],
                         a0, a1, a2, a3, bh[nf * 2], bh[nf * 2 + 1]);
        }
        __syncthreads();               // done reading slot c%3 before it is refilled
    }

#pragma unroll
    for (int mf = 0; mf < 4; mf++) {
#pragma unroll
        for (int nf = 0; nf < 4; nf++) {
            int m0 = bm + wm * 64 + mf * 16 + (lane >> 2);
            int col = bn + wn * 32 + nf * 8 + (lane & 3) * 2;
            float2 bb = *(const float2*)&bias[col];
            float2 v0, v1;
            v0.x = acc[mf][nf][0] + bb.x;
            v0.y = acc[mf][nf][1] + bb.y;
            v1.x = acc[mf][nf][2] + bb.x;
            v1.y = acc[mf][nf][3] + bb.y;
            if (MODE == 0) {
                int part = col >> 10;
                int h = (col >> 6) & (HEADS - 1);
                int d = col & 63;
                float* base = &g_qkv[(((size_t)part * HEADS + h) * NTOK) * HD + d];
                *(float2*)(base + (size_t)m0 * HD) = v0;
                *(float2*)(base + (size_t)(m0 + 8) * HD) = v1;
            } else {
                *(float2*)&Cout[(size_t)m0 * Nc + col] = v0;
                *(float2*)&Cout[(size_t)(m0 + 8) * Nc + col] = v1;
            }
        }
    }
}

// ---------------------------------------------------------------------------
// LayerNorm + bf16 hi/lo split of q, k, and passthrough split of v.
// ---------------------------------------------------------------------------
__global__ void __launch_bounds__(256)
ln2_kernel(const float* __restrict__ qg, const float* __restrict__ qb,
           const float* __restrict__ kg, const float* __restrict__ kb)
{
    const int HN = HEADS * NTOK;
    int warp = (blockIdx.x * blockDim.x + threadIdx.x) >> 5;
    int lane = threadIdx.x & 31;
    if (warp >= 3 * HN) return;

    const float* v = g_qkv + (size_t)warp * HD;
    float2 x = *(const float2*)&v[lane * 2];
    int part = warp / HN;
    int local = warp - part * HN;

    if (part < 2) {
        float s = x.x + x.y;
#pragma unroll
        for (int o = 16; o; o >>= 1) s += __shfl_xor_sync(0xffffffffu, s, o);
        float mu = s * (1.f / 64.f);
        float dx = x.x - mu, dy = x.y - mu;
        float ss = dx * dx + dy * dy;
#pragma unroll
        for (int o = 16; o; o >>= 1) ss += __shfl_xor_sync(0xffffffffu, ss, o);
        float rstd = rsqrtf(ss * (1.f / 64.f) + 1e-6f);
        const float* g = (part == 0) ? qg : kg;
        const float* b = (part == 0) ? qb : kb;
        x.x = dx * rstd * g[lane * 2] + b[lane * 2];
        x.y = dy * rstd * g[lane * 2 + 1] + b[lane * 2 + 1];
    }

    __nv_bfloat16* hi = (part == 0) ? g_qhi : (part == 1) ? g_khi : g_vhi;
    __nv_bfloat16* lo = (part == 0) ? g_qlo : (part == 1) ? g_klo : g_vlo;
    __nv_bfloat16 h0 = __float2bfloat16_rn(x.x);
    __nv_bfloat16 h1 = __float2bfloat16_rn(x.y);
    __nv_bfloat16 l0 = __float2bfloat16_rn(x.x - __bfloat162float(h0));
    __nv_bfloat16 l1 = __float2bfloat16_rn(x.y - __bfloat162float(h1));
    __nv_bfloat162 ph; ph.x = h0; ph.y = h1;
    __nv_bfloat162 pl; pl.x = l0; pl.y = l1;
    *(__nv_bfloat162*)&hi[(size_t)local * HD + lane * 2] = ph;
    *(__nv_bfloat162*)&lo[(size_t)local * HD + lane * 2] = pl;
}

// ---------------------------------------------------------------------------
// HMMA flash attention (unchanged from R6 WIN).
// ---------------------------------------------------------------------------
#define AST 72
#define QLO_ELEMS (224 * AST)
#define KARR (KT * AST)
#define TILE_OFF QLO_ELEMS
#define BIAS_OFF (QLO_ELEMS + 4 * KARR)
#define AT_SMEM_BYTES (BIAS_OFF * 2 + KT * 4 + 16)

__global__ void __launch_bounds__(224, 1)
attn4_kernel(const int* __restrict__ gidx, const float* __restrict__ abias)
{
    extern __shared__ __nv_bfloat16 smb2[];
    __nv_bfloat16* Qlo = smb2;
    __nv_bfloat16* Tile = smb2 + TILE_OFF;
    float* Bs = (float*)(smb2 + BIAS_OFF);
    const uint32_t su = smem_u32(smb2);

    const int s = blockIdx.x, h = blockIdx.y;
    const int tid = threadIdx.x, wid = tid >> 5, lane = tid & 31;
    const int m0 = wid * 32;

    const __nv_bfloat16* qh  = g_qhi + ((size_t)h * NTOK + (size_t)s * PTOK) * HD;
    const __nv_bfloat16* qlg = g_qlo + ((size_t)h * NTOK + (size_t)s * PTOK) * HD;
    const __nv_bfloat16* kh = g_khi + (size_t)h * NTOK * HD;
    const __nv_bfloat16* kl = g_klo + (size_t)h * NTOK * HD;
    const __nv_bfloat16* vh = g_vhi + (size_t)h * NTOK * HD;
    const __nv_bfloat16* vl = g_vlo + (size_t)h * NTOK * HD;

    {
        int row = tid;
        int srcr = row < PTOK ? row : PTOK - 1;
        const uint4* p = (const uint4*)(qlg + (size_t)srcr * HD);
#pragma unroll
        for (int j = 0; j < 8; j++)
            *(uint4*)&Qlo[row * AST + j * 8] = p[j];
    }

    uint32_t qf[2][4][4];
    {
        int r = lane >> 2, c2 = (lane & 3) * 2;
#pragma unroll
        for (int mf = 0; mf < 2; mf++) {
            int r0 = m0 + mf * 16 + r;
            int r1 = r0 + 8;
            if (r0 > PTOK - 1) r0 = PTOK - 1;
            if (r1 > PTOK - 1) r1 = PTOK - 1;
#pragma unroll
            for (int kf = 0; kf < 4; kf++) {
                int c0 = kf * 16 + c2;
                qf[mf][kf][0] = *(const uint32_t*)(qh + (size_t)r0 * HD + c0);
                qf[mf][kf][1] = *(const uint32_t*)(qh + (size_t)r1 * HD + c0);
                qf[mf][kf][2] = *(const uint32_t*)(qh + (size_t)r0 * HD + c0 + 8);
                qf[mf][kf][3] = *(const uint32_t*)(qh + (size_t)r1 * HD + c0 + 8);
            }
        }
    }

    float o[2][8][4];
    float lsum[2][2];
#pragma unroll
    for (int mf = 0; mf < 2; mf++) {
        lsum[mf][0] = 0.f; lsum[mf][1] = 0.f;
#pragma unroll
        for (int nf = 0; nf < 8; nf++)
#pragma unroll
            for (int e = 0; e < 4; e++) o[mf][nf][e] = 0.f;
    }

    const int gbase = s * MKV;

    const uint32_t kaddr = su + 2 * (TILE_OFF
        + ((lane & 7) + ((lane >> 4) & 1) * 8) * AST + ((lane >> 3) & 1) * 8);
    const uint32_t vaddr = su + 2 * (TILE_OFF + 2 * KARR
        + ((lane & 7) + ((lane >> 3) & 1) * 8) * AST + ((lane >> 4) & 1) * 8);
    const uint32_t qladdr = su + 2 * ((m0 + (lane & 15)) * AST + (lane >> 4) * 8);

    uint4 pf[5];
    float pbias = 0.f;
#pragma unroll
    for (int it = 0; it < 5; it++) {
        int slot = tid + it * 224;
        if (slot < 1024) {
            int a = slot >> 8, r = (slot >> 3) & 31, seg = slot & 7;
            int gpos = r;
            int tok = gidx[gbase + (gpos < MKV ? gpos : 0)];
            const __nv_bfloat16* bp = (a == 0) ? kh : (a == 1) ? kl : (a == 2) ? vh : vl;
            pf[it] = *(const uint4*)(bp + (size_t)tok * HD + seg * 8);
        }
    }
    if (tid < KT) pbias = (tid < MKV) ? abias[gbase + tid] - 10.f : -1e9f;

    for (int t = 0; t < NT; t++) {
        __syncthreads();
#pragma unroll
        for (int it = 0; it < 5; it++) {
            int slot = tid + it * 224;
            if (slot < 1024) {
                int a = slot >> 8, r = (slot >> 3) & 31, seg = slot & 7;
                *(uint4*)&Tile[a * KARR + r * AST + seg * 8] = pf[it];
            }
        }
        if (tid < KT) Bs[tid] = pbias;
        __syncthreads();

        if (t + 1 < NT) {
            int t0n = (t + 1) * KT;
#pragma unroll
            for (int it = 0; it < 5; it++) {
                int slot = tid + it * 224;
                if (slot < 1024) {
                    int a = slot >> 8, r = (slot >> 3) & 31, seg = slot & 7;
                    int gpos = t0n + r;
                    int tok = gidx[gbase + (gpos < MKV ? gpos : 0)];
                    const __nv_bfloat16* bp = (a == 0) ? kh : (a == 1) ? kl : (a == 2) ? vh : vl;
                    pf[it] = *(const uint4*)(bp + (size_t)tok * HD + seg * 8);
                }
            }
            if (tid < KT) {
                int gp = t0n + tid;
                pbias = (gp < MKV) ? abias[gbase + gp] - 10.f : -1e9f;
            }
        }

        float sc[2][4][4];
#pragma unroll
        for (int mf = 0; mf < 2; mf++)
#pragma unroll
            for (int nf = 0; nf < 4; nf++)
#pragma unroll
                for (int e = 0; e < 4; e++) sc[mf][nf][e] = 0.f;

#pragma unroll
        for (int kf = 0; kf < 4; kf++) {
            uint32_t bh0[4], bh1[4], bl0[4], bl1[4];
            ldsm4(kaddr + kf * 32, bh0[0], bh0[1], bh0[2], bh0[3]);
            ldsm4(kaddr + kf * 32 + 16 * AST * 2, bh1[0], bh1[1], bh1[2], bh1[3]);
            ldsm4(kaddr + KARR * 2 + kf * 32, bl0[0], bl0[1], bl0[2], bl0[3]);
            ldsm4(kaddr + KARR * 2 + kf * 32 + 16 * AST * 2, bl1[0], bl1[1], bl1[2], bl1[3]);
#pragma unroll
            for (int mf = 0; mf < 2; mf++) {
                uint32_t q0 = qf[mf][kf][0], q1 = qf[mf][kf][1];
                uint32_t q2 = qf[mf][kf][2], q3 = qf[mf][kf][3];
                mma_bf16(sc[mf][0][0], sc[mf][0][1], sc[mf][0][2], sc[mf][0][3],
                         q0, q1, q2, q3, bh0[0], bh0[1]);
                mma_bf16(sc[mf][1][0], sc[mf][1][1], sc[mf][1][2], sc[mf][1][3],
                         q0, q1, q2, q3, bh0[2], bh0[3]);
                mma_bf16(sc[mf][2][0], sc[mf][2][1], sc[mf][2][2], sc[mf][2][3],
                         q0, q1, q2, q3, bh1[0], bh1[1]);
                mma_bf16(sc[mf][3][0], sc[mf][3][1], sc[mf][3][2], sc[mf][3][3],
                         q0, q1, q2, q3, bh1[2], bh1[3]);
                mma_bf16(sc[mf][0][0], sc[mf][0][1], sc[mf][0][2], sc[mf][0][3],
                         q0, q1, q2, q3, bl0[0], bl0[1]);
                mma_bf16(sc[mf][1][0], sc[mf][1][1], sc[mf][1][2], sc[mf][1][3],
                         q0, q1, q2, q3, bl0[2], bl0[3]);
                mma_bf16(sc[mf][2][0], sc[mf][2][1], sc[mf][2][2], sc[mf][2][3],
                         q0, q1, q2, q3, bl1[0], bl1[1]);
                mma_bf16(sc[mf][3][0], sc[mf][3][1], sc[mf][3][2], sc[mf][3][3],
                         q0, q1, q2, q3, bl1[2], bl1[3]);
                uint32_t ql0, ql1, ql2, ql3;
                ldsm4(qladdr + mf * 16 * AST * 2 + kf * 32, ql0, ql1, ql2, ql3);
                mma_bf16(sc[mf][0][0], sc[mf][0][1], sc[mf][0][2], sc[mf][0][3],
                         ql0, ql1, ql2, ql3, bh0[0], bh0[1]);
                mma_bf16(sc[mf][1][0], sc[mf][1][1], sc[mf][1][2], sc[mf][1][3],
                         ql0, ql1, ql2, ql3, bh0[2], bh0[3]);
                mma_bf16(sc[mf][2][0], sc[mf][2][1], sc[mf][2][2], sc[mf][2][3],
                         ql0, ql1, ql2, ql3, bh1[0], bh1[1]);
                mma_bf16(sc[mf][3][0], sc[mf][3][1], sc[mf][3][2], sc[mf][3][3],
                         ql0, ql1, ql2, ql3, bh1[2], bh1[3]);
            }
        }

        uint32_t phi[2][2][4], plo[2][2][4];
#pragma unroll
        for (int mf = 0; mf < 2; mf++) {
#pragma unroll
            for (int nf = 0; nf < 4; nf++) {
                float2 bb = *(const float2*)&Bs[nf * 8 + (lane & 3) * 2];
                float p0 = __expf(fmaf(sc[mf][nf][0], 0.125f, bb.x));
                float p1 = __expf(fmaf(sc[mf][nf][1], 0.125f, bb.y));
                float p2 = __expf(fmaf(sc[mf][nf][2], 0.125f, bb.x));
                float p3 = __expf(fmaf(sc[mf][nf][3], 0.125f, bb.y));
                lsum[mf][0] += p0 + p1;
                lsum[mf][1] += p2 + p3;
                uint32_t h01 = pack_bf16(p0, p1);
                uint32_t h23 = pack_bf16(p2, p3);
                __nv_bfloat162 hv01 = *(__nv_bfloat162*)&h01;
                __nv_bfloat162 hv23 = *(__nv_bfloat162*)&h23;
                uint32_t l01 = pack_bf16(p0 - __bfloat162float(hv01.x),
                                         p1 - __bfloat162float(hv01.y));
                uint32_t l23 = pack_bf16(p2 - __bfloat162float(hv23.x),
                                         p3 - __bfloat162float(hv23.y));
                int kf2 = nf >> 1, hf = (nf & 1) * 2;
                phi[mf][kf2][hf] = h01; phi[mf][kf2][hf + 1] = h23;
                plo[mf][kf2][hf] = l01; plo[mf][kf2][hf + 1] = l23;
            }
        }

#pragma unroll
        for (int kf = 0; kf < 2; kf++) {
            uint32_t vhf[16], vlf[16];
#pragma unroll
            for (int db = 0; db < 4; db++) {
                ldsm4t(vaddr + kf * (16 * AST * 2) + db * 32,
                       vhf[db * 4], vhf[db * 4 + 1], vhf[db * 4 + 2], vhf[db * 4 + 3]);
                ldsm4t(vaddr + KARR * 2 + kf * (16 * AST * 2) + db * 32,
                       vlf[db * 4], vlf[db * 4 + 1], vlf[db * 4 + 2], vlf[db * 4 + 3]);
            }
#pragma unroll
            for (int mf = 0; mf < 2; mf++) {
#pragma unroll
                for (int nfd = 0; nfd < 8; nfd++) {
                    int vi = (nfd >> 1) * 4 + (nfd & 1) * 2;
                    mma_bf16(o[mf][nfd][0], o[mf][nfd][1], o[mf][nfd][2], o[mf][nfd][3],
                             phi[mf][kf][0], phi[mf][kf][1], phi[mf][kf][2], phi[mf][kf][3],
                             vhf[vi], vhf[vi + 1]);
                    mma_bf16(o[mf][nfd][0], o[mf][nfd][1], o[mf][nfd][2], o[mf][nfd][3],
                             phi[mf][kf][0], phi[mf][kf][1], phi[mf][kf][2], phi[mf][kf][3],
                             vlf[vi], vlf[vi + 1]);
                    mma_bf16(o[mf][nfd][0], o[mf][nfd][1], o[mf][nfd][2], o[mf][nfd][3],
                             plo[mf][kf][0], plo[mf][kf][1], plo[mf][kf][2], plo[mf][kf][3],
                             vhf[vi], vhf[vi + 1]);
                }
            }
        }
    }

#pragma unroll
    for (int mf = 0; mf < 2; mf++) {
#pragma unroll
        for (int j = 0; j < 2; j++) {
            float v = lsum[mf][j];
            v += __shfl_xor_sync(0xffffffffu, v, 1);
            v += __shfl_xor_sync(0xffffffffu, v, 2);
            lsum[mf][j] = v;
        }
    }

    {
        int r = lane >> 2, c2 = (lane & 3) * 2;
#pragma unroll
        for (int mf = 0; mf < 2; mf++) {
            int rowq0 = m0 + mf * 16 + r;
            int rowq1 = rowq0 + 8;
            float i0 = 1.f / lsum[mf][0];
            float i1 = 1.f / lsum[mf][1];
            if (rowq0 < PTOK) {
                size_t base = (size_t)(s * PTOK + rowq0) * CDIM + h * HD + c2;
#pragma unroll
                for (int nfd = 0; nfd < 8; nfd++) {
                    float f0 = o[mf][nfd][0] * i0;
                    float f1 = o[mf][nfd][1] * i0;
                    uint32_t hp = pack_bf16(f0, f1);
                    __nv_bfloat162 hv = *(__nv_bfloat162*)&hp;
                    uint32_t lp = pack_bf16(f0 - __bfloat162float(hv.x),
                                            f1 - __bfloat162float(hv.y));
                    *(uint32_t*)&g_ahi[base + nfd * 8] = hp;
                    *(uint32_t*)&g_alo[base + nfd * 8] = lp;
                }
            }
            if (rowq1 < PTOK) {
                size_t base = (size_t)(s * PTOK + rowq1) * CDIM + h * HD + c2;
#pragma unroll
                for (int nfd = 0; nfd < 8; nfd++) {
                    float f0 = o[mf][nfd][2] * i1;
                    float f1 = o[mf][nfd][3] * i1;
                    uint32_t hp = pack_bf16(f0, f1);
                    __nv_bfloat162 hv = *(__nv_bfloat162*)&hp;
                    uint32_t lp = pack_bf16(f0 - __bfloat162float(hv.x),
                                            f1 - __bfloat162float(hv.y));
                    *(uint32_t*)&g_ahi[base + nfd * 8] = hp;
                    *(uint32_t*)&g_alo[base + nfd * 8] = lp;
                }
            }
        }
    }
}

// ---------------------------------------------------------------------------
extern "C" void kernel_launch(void* const* d_in, const int* in_sizes, int n_in,
                              void* d_out, int out_size)
{
    const float* x     = (const float*)d_in[0];
    const float* Wqkv  = (const float*)d_in[1];
    const float* bqkv  = (const float*)d_in[2];
    const float* qg    = (const float*)d_in[3];
    const float* qb    = (const float*)d_in[4];
    const float* kg    = (const float*)d_in[5];
    const float* kb    = (const float*)d_in[6];
    const float* Wproj = (const float*)d_in[7];
    const float* bproj = (const float*)d_in[8];
    const int*   gidx  = (const int*)d_in[9];
    const float* abias = (const float*)d_in[10];
    float* out = (float*)d_out;

    static int attr_set = 0;
    if (!attr_set) {
        cudaFuncSetAttribute(hmma_gemm_kernel<0>,
                             cudaFuncAttributeMaxDynamicSharedMemorySize, GEMM_SMEM);
        cudaFuncSetAttribute(hmma_gemm_kernel<1>,
                             cudaFuncAttributeMaxDynamicSharedMemorySize, GEMM_SMEM);
        cudaFuncSetAttribute(attn4_kernel,
                             cudaFuncAttributeMaxDynamicSharedMemorySize, AT_SMEM_BYTES);
        attr_set = 1;
    }

    const int n4 = NTOK * KDIM / 4;

    // 0) prep: split x, transpose+split weights
    split_kernel<<<n4 / 256, 256>>>(x, n4);
    wsplit_kernel<0><<<dim3(NQKV / 32, KDIM / 32), 256>>>(Wqkv, NQKV);
    wsplit_kernel<1><<<dim3(1024 / 32, KDIM / 32), 256>>>(Wproj, 1024);

    // 1) QKV GEMM (HMMA, cp.async 3-stage) -> g_qkv fp32
    hmma_gemm_kernel<0><<<dim3(NQKV / 128, NTOK / 128), 256, GEMM_SMEM>>>(
        bqkv, nullptr, NQKV);

    // 2) LayerNorm + bf16 hi/lo split of q/k/v
    {
        int nvec = 3 * HEADS * NTOK;
        ln2_kernel<<<(nvec * 32 + 255) / 256, 256>>>(qg, qb, kg, kb);
    }

    // 3) HMMA flash attention -> writes g_ahi/g_alo directly
    attn4_kernel<<<dim3(SFR, HEADS), 224, AT_SMEM_BYTES>>>(gidx, abias);

    // 4) proj GEMM (HMMA, cp.async 3-stage) -> d_out
    hmma_gemm_kernel<1><<<dim3(1024 / 128, NTOK / 128), 256, GEMM_SMEM>>>(
        bproj, out, 1024);
}